// round 1
// baseline (speedup 1.0000x reference)
#include <cuda_runtime.h>

#define BB 2
#define SS 2048
#define DIM 2048
#define NH 16
#define HD 128
#define RANK 32
#define MROWS (BB*SS)

// -------- scratch (device globals; no allocation allowed) --------
__device__ float g_q [MROWS*DIM];
__device__ float g_k [MROWS*DIM];
__device__ float g_v [MROWS*DIM];
__device__ float g_ao[MROWS*DIM];
__device__ float g_qh[MROWS*RANK];
__device__ float g_kh[MROWS*RANK];

// ============================================================
// Generic SGEMM: C[M,N] = A[M,K] * B[N,K]^T   (all row-major)
// BM=BN=128, BK=16, 256 threads, 8x8 per thread.
// Requires M%128==0, N%128==0, K%16==0.
// ============================================================
#define GBM 128
#define GBN 128
#define GBK 16

__global__ __launch_bounds__(256) void sgemm_nt(const float* __restrict__ A,
                                                const float* __restrict__ Bm,
                                                float* __restrict__ C,
                                                int N, int K) {
    __shared__ float As[GBK][GBM + 4];
    __shared__ float Bs[GBK][GBN + 4];
    const int tid = threadIdx.x;
    const int tx = tid & 15, ty = tid >> 4;
    const int lrow = tid >> 2;          // 0..63
    const int lcol = (tid & 3) << 2;    // 0,4,8,12

    const float* Ab = A + (size_t)(blockIdx.y * GBM) * K;
    const float* Bb = Bm + (size_t)(blockIdx.x * GBN) * K;

    float acc[8][8];
#pragma unroll
    for (int i = 0; i < 8; i++)
#pragma unroll
        for (int j = 0; j < 8; j++) acc[i][j] = 0.f;

    for (int k0 = 0; k0 < K; k0 += GBK) {
        float4 a0 = *(const float4*)(Ab + (size_t)lrow * K + k0 + lcol);
        float4 a1 = *(const float4*)(Ab + (size_t)(lrow + 64) * K + k0 + lcol);
        float4 b0 = *(const float4*)(Bb + (size_t)lrow * K + k0 + lcol);
        float4 b1 = *(const float4*)(Bb + (size_t)(lrow + 64) * K + k0 + lcol);
        __syncthreads();
        As[lcol + 0][lrow] = a0.x; As[lcol + 1][lrow] = a0.y;
        As[lcol + 2][lrow] = a0.z; As[lcol + 3][lrow] = a0.w;
        As[lcol + 0][lrow + 64] = a1.x; As[lcol + 1][lrow + 64] = a1.y;
        As[lcol + 2][lrow + 64] = a1.z; As[lcol + 3][lrow + 64] = a1.w;
        Bs[lcol + 0][lrow] = b0.x; Bs[lcol + 1][lrow] = b0.y;
        Bs[lcol + 2][lrow] = b0.z; Bs[lcol + 3][lrow] = b0.w;
        Bs[lcol + 0][lrow + 64] = b1.x; Bs[lcol + 1][lrow + 64] = b1.y;
        Bs[lcol + 2][lrow + 64] = b1.z; Bs[lcol + 3][lrow + 64] = b1.w;
        __syncthreads();
#pragma unroll
        for (int kk = 0; kk < GBK; kk++) {
            float ra[8], rb[8];
            *(float4*)(ra)     = *(const float4*)&As[kk][ty * 8];
            *(float4*)(ra + 4) = *(const float4*)&As[kk][ty * 8 + 4];
            *(float4*)(rb)     = *(const float4*)&Bs[kk][tx * 8];
            *(float4*)(rb + 4) = *(const float4*)&Bs[kk][tx * 8 + 4];
#pragma unroll
            for (int i = 0; i < 8; i++)
#pragma unroll
                for (int j = 0; j < 8; j++)
                    acc[i][j] = fmaf(ra[i], rb[j], acc[i][j]);
        }
    }
#pragma unroll
    for (int i = 0; i < 8; i++) {
        size_t base = (size_t)(blockIdx.y * GBM + ty * 8 + i) * N + blockIdx.x * GBN + tx * 8;
        *(float4*)&C[base]     = make_float4(acc[i][0], acc[i][1], acc[i][2], acc[i][3]);
        *(float4*)&C[base + 4] = make_float4(acc[i][4], acc[i][5], acc[i][6], acc[i][7]);
    }
}

// ============================================================
// LoRA projection: C[M,32] = X[M,2048] * W[32,2048]^T
// One block = 32 m-rows, 256 threads.
// ============================================================
__global__ __launch_bounds__(256) void lora_gemm(const float* __restrict__ X,
                                                 const float* __restrict__ W,
                                                 float* __restrict__ C) {
    __shared__ float xs[32][33];
    __shared__ float ws[32][33];
    const int tid = threadIdx.x;
    const int lane = tid & 31, wrp = tid >> 5;  // 8 warps, each owns 4 m-rows
    const int m0 = blockIdx.x * 32;
    float acc[4] = {0.f, 0.f, 0.f, 0.f};

    for (int k0 = 0; k0 < DIM; k0 += 32) {
        __syncthreads();
#pragma unroll
        for (int l = 0; l < 4; l++) {
            int lin = l * 256 + tid;
            int r = lin >> 5, c = lin & 31;
            xs[r][c] = X[(size_t)(m0 + r) * DIM + k0 + c];
            ws[r][c] = W[(size_t)r * DIM + k0 + c];
        }
        __syncthreads();
#pragma unroll
        for (int kk = 0; kk < 32; kk++) {
            float wv = ws[lane][kk];
#pragma unroll
            for (int i = 0; i < 4; i++)
                acc[i] = fmaf(xs[wrp * 4 + i][kk], wv, acc[i]);
        }
    }
#pragma unroll
    for (int i = 0; i < 4; i++)
        C[(size_t)(m0 + wrp * 4 + i) * RANK + lane] = acc[i];
}

// ============================================================
// RoPE in-place on q and k, layout [B,S,NH*HD]
// one thread per (re,im) pair
// ============================================================
__global__ __launch_bounds__(256) void rope_kernel(float* __restrict__ q,
                                                   float* __restrict__ k,
                                                   const float* __restrict__ cs,
                                                   const float* __restrict__ sn) {
    int t = blockIdx.x * 256 + threadIdx.x;      // 0 .. MROWS*DIM/2-1
    int p = t & 63;                              // pair index within head
    int row = t / (DIM / 2);                     // b*S + s
    int s_idx = row & (SS - 1);
    float c = cs[s_idx * 64 + p];
    float si = sn[s_idx * 64 + p];
    float2 v = ((float2*)q)[t];
    float2 o;
    o.x = v.x * c - v.y * si;
    o.y = v.x * si + v.y * c;
    ((float2*)q)[t] = o;
    float2 w = ((float2*)k)[t];
    float2 o2;
    o2.x = w.x * c - w.y * si;
    o2.y = w.x * si + w.y * c;
    ((float2*)k)[t] = o2;
}

// ============================================================
// Flash attention with adaptive sigmoid gate.
// out[q,:] = sum_k softmax(s)_k * sigmoid(qh_q . kh_k) * v_k
// Gate multiplies numerator only -> standard online softmax valid.
// Grid: (S/64, B*NH). 256 threads. BM=BN=64.
// ============================================================
#define FBM 64
#define FBN 64
#define FLASH_SMEM_FLOATS (128*65 + 128*65 + 64*128 + 64*64 + 64*32 + 32*65)

__global__ __launch_bounds__(256) void flash_attn(const float* __restrict__ Q,
                                                  const float* __restrict__ K,
                                                  const float* __restrict__ V,
                                                  const float* __restrict__ QH,
                                                  const float* __restrict__ KH,
                                                  float* __restrict__ O) {
    extern __shared__ float smf[];
    float* Qs  = smf;               // [128][65]  (d-major, padded)
    float* Ks  = Qs + 128 * 65;     // [128][65]
    float* Vs  = Ks + 128 * 65;     // [64][128]  (k-major)
    float* Ps  = Vs + 64 * 128;     // [64][64]
    float* qhs = Ps + 64 * 64;      // [64][32]
    float* khs = qhs + 64 * 32;     // [32][65]

    const int tid = threadIdx.x;
    const int tx = tid & 15, ty = tid >> 4;
    const int b = blockIdx.y >> 4;   // / NH
    const int h = blockIdx.y & 15;
    const int q0 = blockIdx.x * FBM;
    const size_t rowbase = (size_t)b * SS;

    // ---- load Q tile (transposed into smem) + qh tile ----
    {
        const int c = tid & 127, rb = tid >> 7;
#pragma unroll
        for (int l = 0; l < 32; l++) {
            int r = l * 2 + rb;
            Qs[c * 65 + r] = Q[(rowbase + q0 + r) * DIM + h * HD + c];
        }
        const int c2 = tid & 31, rb2 = tid >> 5;
#pragma unroll
        for (int l = 0; l < 8; l++) {
            int r = l * 8 + rb2;
            qhs[r * 32 + c2] = QH[(rowbase + q0 + r) * RANK + c2];
        }
    }

    float m_i[4], l_i[4], acc[4][8];
#pragma unroll
    for (int i = 0; i < 4; i++) {
        m_i[i] = -1e30f;
        l_i[i] = 0.f;
#pragma unroll
        for (int jj = 0; jj < 8; jj++) acc[i][jj] = 0.f;
    }

    const float SC = 0.08838834764831845f;  // 1/sqrt(128)

    for (int k0 = 0; k0 <= q0; k0 += FBN) {
        __syncthreads();  // protect Ks/Vs/khs/Ps from previous iteration readers
        {
            const int c = tid & 127, rb = tid >> 7;
#pragma unroll
            for (int l = 0; l < 32; l++) {
                int r = l * 2 + rb;
                size_t gidx = (rowbase + k0 + r) * DIM + h * HD + c;
                Ks[c * 65 + r]  = K[gidx];
                Vs[r * 128 + c] = V[gidx];
            }
            const int c2 = tid & 31, rb2 = tid >> 5;
#pragma unroll
            for (int l = 0; l < 8; l++) {
                int r = l * 8 + rb2;
                khs[c2 * 65 + r] = KH[(rowbase + k0 + r) * RANK + c2];
            }
        }
        __syncthreads();

        // ---- scores S = Q.K^T over 128 dims ----
        float s[4][4];
#pragma unroll
        for (int i = 0; i < 4; i++)
#pragma unroll
            for (int j = 0; j < 4; j++) s[i][j] = 0.f;
#pragma unroll 8
        for (int d = 0; d < 128; d++) {
            float qa[4], kb[4];
#pragma unroll
            for (int i = 0; i < 4; i++) qa[i] = Qs[d * 65 + ty * 4 + i];
#pragma unroll
            for (int j = 0; j < 4; j++) kb[j] = Ks[d * 65 + tx * 4 + j];
#pragma unroll
            for (int i = 0; i < 4; i++)
#pragma unroll
                for (int j = 0; j < 4; j++) s[i][j] = fmaf(qa[i], kb[j], s[i][j]);
        }

        // ---- adaptive gate logits over 32 ranks ----
        float g[4][4];
#pragma unroll
        for (int i = 0; i < 4; i++)
#pragma unroll
            for (int j = 0; j < 4; j++) g[i][j] = 0.f;
#pragma unroll 8
        for (int r = 0; r < 32; r++) {
            float qa[4], kb[4];
#pragma unroll
            for (int i = 0; i < 4; i++) qa[i] = qhs[(ty * 4 + i) * 32 + r];
#pragma unroll
            for (int j = 0; j < 4; j++) kb[j] = khs[r * 65 + tx * 4 + j];
#pragma unroll
            for (int i = 0; i < 4; i++)
#pragma unroll
                for (int j = 0; j < 4; j++) g[i][j] = fmaf(qa[i], kb[j], g[i][j]);
        }

        // ---- scale + causal mask (only diagonal tile needs masking) ----
        if (k0 == q0) {
#pragma unroll
            for (int i = 0; i < 4; i++)
#pragma unroll
                for (int j = 0; j < 4; j++)
                    s[i][j] = (tx * 4 + j <= ty * 4 + i) ? s[i][j] * SC : -1e9f;
        } else {
#pragma unroll
            for (int i = 0; i < 4; i++)
#pragma unroll
                for (int j = 0; j < 4; j++) s[i][j] *= SC;
        }

        // ---- online softmax update (reduce across 16 tx lanes) ----
#pragma unroll
        for (int i = 0; i < 4; i++) {
            float mx = fmaxf(fmaxf(s[i][0], s[i][1]), fmaxf(s[i][2], s[i][3]));
#pragma unroll
            for (int off = 8; off >= 1; off >>= 1)
                mx = fmaxf(mx, __shfl_xor_sync(0xffffffffu, mx, off));
            float mnew = fmaxf(m_i[i], mx);
            float alpha = __expf(m_i[i] - mnew);
            float p[4], rs = 0.f;
#pragma unroll
            for (int j = 0; j < 4; j++) {
                p[j] = __expf(s[i][j] - mnew);
                rs += p[j];
            }
#pragma unroll
            for (int off = 8; off >= 1; off >>= 1)
                rs += __shfl_xor_sync(0xffffffffu, rs, off);
            l_i[i] = l_i[i] * alpha + rs;
            m_i[i] = mnew;
#pragma unroll
            for (int jj = 0; jj < 8; jj++) acc[i][jj] *= alpha;
            float4 pg;
            pg.x = p[0] / (1.f + __expf(-g[i][0]));
            pg.y = p[1] / (1.f + __expf(-g[i][1]));
            pg.z = p[2] / (1.f + __expf(-g[i][2]));
            pg.w = p[3] / (1.f + __expf(-g[i][3]));
            ((float4*)Ps)[(ty * 4 + i) * 16 + tx] = pg;
        }
        __syncthreads();

        // ---- acc += (P*G) . V ----
#pragma unroll 4
        for (int k = 0; k < 64; k++) {
            float vv[8];
#pragma unroll
            for (int jj = 0; jj < 8; jj++) vv[jj] = Vs[k * 128 + tx + 16 * jj];
#pragma unroll
            for (int i = 0; i < 4; i++) {
                float p = Ps[(ty * 4 + i) * 64 + k];
#pragma unroll
                for (int jj = 0; jj < 8; jj++)
                    acc[i][jj] = fmaf(p, vv[jj], acc[i][jj]);
            }
        }
    }

    // ---- epilogue: normalize and write ----
#pragma unroll
    for (int i = 0; i < 4; i++) {
        float inv = 1.f / l_i[i];
#pragma unroll
        for (int jj = 0; jj < 8; jj++)
            O[(rowbase + q0 + ty * 4 + i) * DIM + h * HD + tx + 16 * jj] = acc[i][jj] * inv;
    }
}

// ============================================================
// launch
// ============================================================
extern "C" void kernel_launch(void* const* d_in, const int* in_sizes, int n_in,
                              void* d_out, int out_size) {
    const float* x    = (const float*)d_in[0];
    // d_in[1] = mask (built-in causal used instead; values identical)
    const float* fcos = (const float*)d_in[2];
    const float* fsin = (const float*)d_in[3];
    const float* wq   = (const float*)d_in[4];
    const float* wk   = (const float*)d_in[5];
    const float* wv   = (const float*)d_in[6];
    const float* wo   = (const float*)d_in[7];
    const float* waq  = (const float*)d_in[8];
    const float* wak  = (const float*)d_in[9];
    float* out = (float*)d_out;

    float *gq, *gk, *gv, *gao, *gqh, *gkh;
    cudaGetSymbolAddress((void**)&gq,  g_q);
    cudaGetSymbolAddress((void**)&gk,  g_k);
    cudaGetSymbolAddress((void**)&gv,  g_v);
    cudaGetSymbolAddress((void**)&gao, g_ao);
    cudaGetSymbolAddress((void**)&gqh, g_qh);
    cudaGetSymbolAddress((void**)&gkh, g_kh);

    const int fsm = FLASH_SMEM_FLOATS * (int)sizeof(float);
    cudaFuncSetAttribute(flash_attn, cudaFuncAttributeMaxDynamicSharedMemorySize, fsm);

    dim3 gg(DIM / GBN, MROWS / GBM);
    sgemm_nt<<<gg, 256>>>(x, wq, gq, DIM, DIM);
    sgemm_nt<<<gg, 256>>>(x, wk, gk, DIM, DIM);
    sgemm_nt<<<gg, 256>>>(x, wv, gv, DIM, DIM);
    lora_gemm<<<MROWS / 32, 256>>>(x, waq, gqh);
    lora_gemm<<<MROWS / 32, 256>>>(x, wak, gkh);
    rope_kernel<<<MROWS * (DIM / 2) / 256, 256>>>(gq, gk, fcos, fsin);
    flash_attn<<<dim3(SS / FBM, BB * NH), 256, fsm>>>(gq, gk, gv, gqh, gkh, gao);
    sgemm_nt<<<gg, 256>>>(gao, wo, out, DIM, DIM);
}

// round 3
// speedup vs baseline: 1.5500x; 1.5500x over previous
#include <cuda_runtime.h>
#include <cuda_bf16.h>
#include <cstdint>

#define BB 2
#define SS 2048
#define DIM 2048
#define NH 16
#define HD 128
#define RANK 32
#define MROWS (BB*SS)

// -------- scratch (device globals; no allocation allowed) --------
__device__ float g_q [MROWS*DIM];
__device__ float g_k [MROWS*DIM];
__device__ float g_v [MROWS*DIM];
__device__ float g_ao[MROWS*DIM];
__device__ float g_qh[MROWS*RANK];
__device__ float g_kh[MROWS*RANK];
// bf16 hi/lo pairs
__device__ __nv_bfloat16 g_xh [MROWS*DIM];
__device__ __nv_bfloat16 g_xl [MROWS*DIM];
__device__ __nv_bfloat16 g_aoh[MROWS*DIM];
__device__ __nv_bfloat16 g_aol[MROWS*DIM];
__device__ __nv_bfloat16 g_wh [4][DIM*DIM];
__device__ __nv_bfloat16 g_wl [4][DIM*DIM];

__device__ __forceinline__ uint32_t smem_to_u32(const void* smem_ptr) {
    uint32_t addr;
    asm("{ .reg .u64 tmp; cvta.to.shared.u64 tmp, %1; cvt.u32.u64 %0, tmp; }"
        : "=r"(addr) : "l"(smem_ptr));
    return addr;
}

__device__ __forceinline__ void ldsm_x4(uint32_t& d0, uint32_t& d1, uint32_t& d2,
                                        uint32_t& d3, uint32_t addr) {
    asm volatile("ldmatrix.sync.aligned.m8n8.x4.shared.b16 {%0,%1,%2,%3}, [%4];"
                 : "=r"(d0), "=r"(d1), "=r"(d2), "=r"(d3) : "r"(addr));
}

__device__ __forceinline__ void mma_bf16(float* c, const uint32_t* a,
                                         uint32_t b0, uint32_t b1) {
    asm volatile("mma.sync.aligned.m16n8k16.row.col.f32.bf16.bf16.f32 "
                 "{%0,%1,%2,%3}, {%4,%5,%6,%7}, {%8,%9}, {%0,%1,%2,%3};"
                 : "+f"(c[0]), "+f"(c[1]), "+f"(c[2]), "+f"(c[3])
                 : "r"(a[0]), "r"(a[1]), "r"(a[2]), "r"(a[3]), "r"(b0), "r"(b1));
}

// ============================================================
// fp32 -> (bf16 hi, bf16 lo) conversion, vectorized x4
// ============================================================
__global__ __launch_bounds__(256) void f32_to_bf16pair(const float* __restrict__ in,
                                                       __nv_bfloat16* __restrict__ hi,
                                                       __nv_bfloat16* __restrict__ lo) {
    int i = blockIdx.x * 256 + threadIdx.x;
    float4 v = ((const float4*)in)[i];
    __nv_bfloat162 h0, h1, l0, l1;
    h0.x = __float2bfloat16(v.x); h0.y = __float2bfloat16(v.y);
    h1.x = __float2bfloat16(v.z); h1.y = __float2bfloat16(v.w);
    l0.x = __float2bfloat16(v.x - __bfloat162float(h0.x));
    l0.y = __float2bfloat16(v.y - __bfloat162float(h0.y));
    l1.x = __float2bfloat16(v.z - __bfloat162float(h1.x));
    l1.y = __float2bfloat16(v.w - __bfloat162float(h1.y));
    ((__nv_bfloat162*)hi)[2 * i]     = h0;
    ((__nv_bfloat162*)hi)[2 * i + 1] = h1;
    ((__nv_bfloat162*)lo)[2 * i]     = l0;
    ((__nv_bfloat162*)lo)[2 * i + 1] = l1;
}

// ============================================================
// mma.sync GEMM: C[M,N] = (Ahi+Alo)[M,K] * (Bhi+Blo)[N,K]^T
// hi*hi + hi*lo + lo*hi, fp32 accumulate.
// 128x128 tile, BK=32, 256 thr, 8 warps (2x4 layout, 32x64 warp tile),
// 2-stage cp.async double buffer. K = 2048.
// ============================================================
#define KDIM 2048
#define TBK 32
#define NKIT (KDIM / TBK)
#define LDK 40                 // padded halves per smem row (80 B)
#define TILE_B (128 * LDK * 2) // 10240 B per 128x32 bf16 tile
#define STAGE_B (4 * TILE_B)   // Ahi,Alo,Bhi,Blo
#define TC_SMEM (2 * STAGE_B)  // 81920 B

__global__ __launch_bounds__(256) void tc_gemm(const __nv_bfloat16* __restrict__ Ahi,
                                               const __nv_bfloat16* __restrict__ Alo,
                                               const __nv_bfloat16* __restrict__ Bhi,
                                               const __nv_bfloat16* __restrict__ Blo,
                                               float* __restrict__ C, int N) {
    extern __shared__ char smem[];
    const uint32_t sb = smem_to_u32(smem);
    const int tid = threadIdx.x;
    const int wid = tid >> 5, lane = tid & 31;
    const int m0 = blockIdx.y * 128;
    const int n0 = blockIdx.x * 128;
    const int wm = (wid & 3) * 32;   // warp m offset
    const int wn = (wid >> 2) * 64;  // warp n offset

    const __nv_bfloat16* srcs[4] = {
        Ahi + (size_t)m0 * KDIM, Alo + (size_t)m0 * KDIM,
        Bhi + (size_t)n0 * KDIM, Blo + (size_t)n0 * KDIM };

    // per-thread load slots: 8 chunks of 16B per stage
    int l_tile[8], l_r[8], l_c[8];
#pragma unroll
    for (int u = 0; u < 8; u++) {
        int cid = u * 256 + tid;
        l_tile[u] = cid >> 9;
        int w = cid & 511;
        l_r[u] = w >> 2;
        l_c[u] = w & 3;
    }

    auto issue_stage = [&](int it, int stage) {
        uint32_t base = sb + stage * STAGE_B;
        int k0 = it * TBK;
#pragma unroll
        for (int u = 0; u < 8; u++) {
            uint32_t dst = base + l_tile[u] * TILE_B + l_r[u] * (LDK * 2) + l_c[u] * 16;
            const __nv_bfloat16* src = srcs[l_tile[u]] + (size_t)l_r[u] * KDIM + k0 + l_c[u] * 8;
            asm volatile("cp.async.cg.shared.global [%0], [%1], 16;"
                         :: "r"(dst), "l"(src));
        }
        asm volatile("cp.async.commit_group;" ::: "memory");
    };

    float acc[2][8][4];
#pragma unroll
    for (int i = 0; i < 2; i++)
#pragma unroll
        for (int j = 0; j < 8; j++)
#pragma unroll
            for (int q = 0; q < 4; q++) acc[i][j][q] = 0.f;

    // ldmatrix base offsets for this lane
    const int lrow = lane & 15;          // row within 16-row tile
    const int lcol = (lane >> 4) * 8;    // 0 or 8 (k offset)

    issue_stage(0, 0);

    for (int it = 0; it < NKIT; it++) {
        int cur = it & 1;
        if (it + 1 < NKIT) {
            issue_stage(it + 1, cur ^ 1);
            asm volatile("cp.async.wait_group 1;" ::: "memory");
        } else {
            asm volatile("cp.async.wait_group 0;" ::: "memory");
        }
        __syncthreads();

        uint32_t base = sb + cur * STAGE_B;
        uint32_t aA_hi = base + 0 * TILE_B;
        uint32_t aA_lo = base + 1 * TILE_B;
        uint32_t aB_hi = base + 2 * TILE_B;
        uint32_t aB_lo = base + 3 * TILE_B;

#pragma unroll
        for (int ks = 0; ks < 2; ks++) {
            const int kc = ks * 16 + lcol;
            uint32_t ah[2][4], al[2][4], bh[4][4], bl[4][4];
#pragma unroll
            for (int ma = 0; ma < 2; ma++) {
                uint32_t off = (wm + ma * 16 + lrow) * (LDK * 2) + kc * 2;
                ldsm_x4(ah[ma][0], ah[ma][1], ah[ma][2], ah[ma][3], aA_hi + off);
                ldsm_x4(al[ma][0], al[ma][1], al[ma][2], al[ma][3], aA_lo + off);
            }
#pragma unroll
            for (int nb = 0; nb < 4; nb++) {
                uint32_t off = (wn + nb * 16 + lrow) * (LDK * 2) + kc * 2;
                ldsm_x4(bh[nb][0], bh[nb][1], bh[nb][2], bh[nb][3], aB_hi + off);
                ldsm_x4(bl[nb][0], bl[nb][1], bl[nb][2], bl[nb][3], aB_lo + off);
            }
#pragma unroll
            for (int ma = 0; ma < 2; ma++)
#pragma unroll
                for (int nb = 0; nb < 4; nb++) {
                    // atom (n low 8): b = {frag0, frag2}; atom (n high 8): {frag1, frag3}
                    mma_bf16(acc[ma][nb * 2],     ah[ma], bh[nb][0], bh[nb][2]);
                    mma_bf16(acc[ma][nb * 2 + 1], ah[ma], bh[nb][1], bh[nb][3]);
                    mma_bf16(acc[ma][nb * 2],     ah[ma], bl[nb][0], bl[nb][2]);
                    mma_bf16(acc[ma][nb * 2 + 1], ah[ma], bl[nb][1], bl[nb][3]);
                    mma_bf16(acc[ma][nb * 2],     al[ma], bh[nb][0], bh[nb][2]);
                    mma_bf16(acc[ma][nb * 2 + 1], al[ma], bh[nb][1], bh[nb][3]);
                }
        }
        __syncthreads();
    }

    // epilogue: C fragment layout m16n8: rows lane>>2 (+8), cols (lane&3)*2 (+1)
    const int er = lane >> 2;
    const int ec = (lane & 3) * 2;
#pragma unroll
    for (int ma = 0; ma < 2; ma++) {
#pragma unroll
        for (int na = 0; na < 8; na++) {
            int row = m0 + wm + ma * 16 + er;
            int col = n0 + wn + na * 8 + ec;
            float* p0 = C + (size_t)row * N + col;
            float* p1 = C + (size_t)(row + 8) * N + col;
            p0[0] = acc[ma][na][0]; p0[1] = acc[ma][na][1];
            p1[0] = acc[ma][na][2]; p1[1] = acc[ma][na][3];
        }
    }
}

// ============================================================
// LoRA projection: C[M,32] = X[M,2048] * W[32,2048]^T
// ============================================================
__global__ __launch_bounds__(256) void lora_gemm(const float* __restrict__ X,
                                                 const float* __restrict__ W,
                                                 float* __restrict__ C) {
    __shared__ float xs[32][33];
    __shared__ float ws[32][33];
    const int tid = threadIdx.x;
    const int lane = tid & 31, wrp = tid >> 5;
    const int m0 = blockIdx.x * 32;
    float acc[4] = {0.f, 0.f, 0.f, 0.f};

    for (int k0 = 0; k0 < DIM; k0 += 32) {
        __syncthreads();
#pragma unroll
        for (int l = 0; l < 4; l++) {
            int lin = l * 256 + tid;
            int r = lin >> 5, c = lin & 31;
            xs[r][c] = X[(size_t)(m0 + r) * DIM + k0 + c];
            ws[r][c] = W[(size_t)r * DIM + k0 + c];
        }
        __syncthreads();
#pragma unroll
        for (int kk = 0; kk < 32; kk++) {
            float wv = ws[lane][kk];
#pragma unroll
            for (int i = 0; i < 4; i++)
                acc[i] = fmaf(xs[wrp * 4 + i][kk], wv, acc[i]);
        }
    }
#pragma unroll
    for (int i = 0; i < 4; i++)
        C[(size_t)(m0 + wrp * 4 + i) * RANK + lane] = acc[i];
}

// ============================================================
// RoPE in-place on q and k
// ============================================================
__global__ __launch_bounds__(256) void rope_kernel(float* __restrict__ q,
                                                   float* __restrict__ k,
                                                   const float* __restrict__ cs,
                                                   const float* __restrict__ sn) {
    int t = blockIdx.x * 256 + threadIdx.x;
    int p = t & 63;
    int row = t / (DIM / 2);
    int s_idx = row & (SS - 1);
    float c = cs[s_idx * 64 + p];
    float si = sn[s_idx * 64 + p];
    float2 v = ((float2*)q)[t];
    float2 o;
    o.x = v.x * c - v.y * si;
    o.y = v.x * si + v.y * c;
    ((float2*)q)[t] = o;
    float2 w = ((float2*)k)[t];
    float2 o2;
    o2.x = w.x * c - w.y * si;
    o2.y = w.x * si + w.y * c;
    ((float2*)k)[t] = o2;
}

// ============================================================
// Flash attention with adaptive sigmoid gate (fp32 SIMT)
// ============================================================
#define FBM 64
#define FBN 64
#define FLASH_SMEM_FLOATS (128*65 + 128*65 + 64*128 + 64*64 + 64*32 + 32*65)

__global__ __launch_bounds__(256) void flash_attn(const float* __restrict__ Q,
                                                  const float* __restrict__ K,
                                                  const float* __restrict__ V,
                                                  const float* __restrict__ QH,
                                                  const float* __restrict__ KH,
                                                  float* __restrict__ O) {
    extern __shared__ float smf[];
    float* Qs  = smf;
    float* Ks  = Qs + 128 * 65;
    float* Vs  = Ks + 128 * 65;
    float* Ps  = Vs + 64 * 128;
    float* qhs = Ps + 64 * 64;
    float* khs = qhs + 64 * 32;

    const int tid = threadIdx.x;
    const int tx = tid & 15, ty = tid >> 4;
    const int b = blockIdx.y >> 4;
    const int h = blockIdx.y & 15;
    const int q0 = blockIdx.x * FBM;
    const size_t rowbase = (size_t)b * SS;

    {
        const int c = tid & 127, rb = tid >> 7;
#pragma unroll
        for (int l = 0; l < 32; l++) {
            int r = l * 2 + rb;
            Qs[c * 65 + r] = Q[(rowbase + q0 + r) * DIM + h * HD + c];
        }
        const int c2 = tid & 31, rb2 = tid >> 5;
#pragma unroll
        for (int l = 0; l < 8; l++) {
            int r = l * 8 + rb2;
            qhs[r * 32 + c2] = QH[(rowbase + q0 + r) * RANK + c2];
        }
    }

    float m_i[4], l_i[4], acc[4][8];
#pragma unroll
    for (int i = 0; i < 4; i++) {
        m_i[i] = -1e30f;
        l_i[i] = 0.f;
#pragma unroll
        for (int jj = 0; jj < 8; jj++) acc[i][jj] = 0.f;
    }

    const float SC = 0.08838834764831845f;

    for (int k0 = 0; k0 <= q0; k0 += FBN) {
        __syncthreads();
        {
            const int c = tid & 127, rb = tid >> 7;
#pragma unroll
            for (int l = 0; l < 32; l++) {
                int r = l * 2 + rb;
                size_t gidx = (rowbase + k0 + r) * DIM + h * HD + c;
                Ks[c * 65 + r]  = K[gidx];
                Vs[r * 128 + c] = V[gidx];
            }
            const int c2 = tid & 31, rb2 = tid >> 5;
#pragma unroll
            for (int l = 0; l < 8; l++) {
                int r = l * 8 + rb2;
                khs[c2 * 65 + r] = KH[(rowbase + k0 + r) * RANK + c2];
            }
        }
        __syncthreads();

        float s[4][4];
#pragma unroll
        for (int i = 0; i < 4; i++)
#pragma unroll
            for (int j = 0; j < 4; j++) s[i][j] = 0.f;
#pragma unroll 8
        for (int d = 0; d < 128; d++) {
            float qa[4], kb[4];
#pragma unroll
            for (int i = 0; i < 4; i++) qa[i] = Qs[d * 65 + ty * 4 + i];
#pragma unroll
            for (int j = 0; j < 4; j++) kb[j] = Ks[d * 65 + tx * 4 + j];
#pragma unroll
            for (int i = 0; i < 4; i++)
#pragma unroll
                for (int j = 0; j < 4; j++) s[i][j] = fmaf(qa[i], kb[j], s[i][j]);
        }

        float g[4][4];
#pragma unroll
        for (int i = 0; i < 4; i++)
#pragma unroll
            for (int j = 0; j < 4; j++) g[i][j] = 0.f;
#pragma unroll 8
        for (int r = 0; r < 32; r++) {
            float qa[4], kb[4];
#pragma unroll
            for (int i = 0; i < 4; i++) qa[i] = qhs[(ty * 4 + i) * 32 + r];
#pragma unroll
            for (int j = 0; j < 4; j++) kb[j] = khs[r * 65 + tx * 4 + j];
#pragma unroll
            for (int i = 0; i < 4; i++)
#pragma unroll
                for (int j = 0; j < 4; j++) g[i][j] = fmaf(qa[i], kb[j], g[i][j]);
        }

        if (k0 == q0) {
#pragma unroll
            for (int i = 0; i < 4; i++)
#pragma unroll
                for (int j = 0; j < 4; j++)
                    s[i][j] = (tx * 4 + j <= ty * 4 + i) ? s[i][j] * SC : -1e9f;
        } else {
#pragma unroll
            for (int i = 0; i < 4; i++)
#pragma unroll
                for (int j = 0; j < 4; j++) s[i][j] *= SC;
        }

#pragma unroll
        for (int i = 0; i < 4; i++) {
            float mx = fmaxf(fmaxf(s[i][0], s[i][1]), fmaxf(s[i][2], s[i][3]));
#pragma unroll
            for (int off = 8; off >= 1; off >>= 1)
                mx = fmaxf(mx, __shfl_xor_sync(0xffffffffu, mx, off));
            float mnew = fmaxf(m_i[i], mx);
            float alpha = __expf(m_i[i] - mnew);
            float p[4], rs = 0.f;
#pragma unroll
            for (int j = 0; j < 4; j++) {
                p[j] = __expf(s[i][j] - mnew);
                rs += p[j];
            }
#pragma unroll
            for (int off = 8; off >= 1; off >>= 1)
                rs += __shfl_xor_sync(0xffffffffu, rs, off);
            l_i[i] = l_i[i] * alpha + rs;
            m_i[i] = mnew;
#pragma unroll
            for (int jj = 0; jj < 8; jj++) acc[i][jj] *= alpha;
            float4 pg;
            pg.x = p[0] / (1.f + __expf(-g[i][0]));
            pg.y = p[1] / (1.f + __expf(-g[i][1]));
            pg.z = p[2] / (1.f + __expf(-g[i][2]));
            pg.w = p[3] / (1.f + __expf(-g[i][3]));
            ((float4*)Ps)[(ty * 4 + i) * 16 + tx] = pg;
        }
        __syncthreads();

#pragma unroll 4
        for (int k = 0; k < 64; k++) {
            float vv[8];
#pragma unroll
            for (int jj = 0; jj < 8; jj++) vv[jj] = Vs[k * 128 + tx + 16 * jj];
#pragma unroll
            for (int i = 0; i < 4; i++) {
                float p = Ps[(ty * 4 + i) * 64 + k];
#pragma unroll
                for (int jj = 0; jj < 8; jj++)
                    acc[i][jj] = fmaf(p, vv[jj], acc[i][jj]);
            }
        }
    }

#pragma unroll
    for (int i = 0; i < 4; i++) {
        float inv = 1.f / l_i[i];
#pragma unroll
        for (int jj = 0; jj < 8; jj++)
            O[(rowbase + q0 + ty * 4 + i) * DIM + h * HD + tx + 16 * jj] = acc[i][jj] * inv;
    }
}

// ============================================================
// launch
// ============================================================
extern "C" void kernel_launch(void* const* d_in, const int* in_sizes, int n_in,
                              void* d_out, int out_size) {
    const float* x    = (const float*)d_in[0];
    const float* fcos = (const float*)d_in[2];
    const float* fsin = (const float*)d_in[3];
    const float* wq   = (const float*)d_in[4];
    const float* wk   = (const float*)d_in[5];
    const float* wv   = (const float*)d_in[6];
    const float* wo   = (const float*)d_in[7];
    const float* waq  = (const float*)d_in[8];
    const float* wak  = (const float*)d_in[9];
    float* out = (float*)d_out;

    float *gq, *gk, *gv, *gao, *gqh, *gkh;
    __nv_bfloat16 *gxh, *gxl, *gaoh, *gaol, *gwh, *gwl;
    cudaGetSymbolAddress((void**)&gq,  g_q);
    cudaGetSymbolAddress((void**)&gk,  g_k);
    cudaGetSymbolAddress((void**)&gv,  g_v);
    cudaGetSymbolAddress((void**)&gao, g_ao);
    cudaGetSymbolAddress((void**)&gqh, g_qh);
    cudaGetSymbolAddress((void**)&gkh, g_kh);
    cudaGetSymbolAddress((void**)&gxh, g_xh);
    cudaGetSymbolAddress((void**)&gxl, g_xl);
    cudaGetSymbolAddress((void**)&gaoh, g_aoh);
    cudaGetSymbolAddress((void**)&gaol, g_aol);
    cudaGetSymbolAddress((void**)&gwh, g_wh);
    cudaGetSymbolAddress((void**)&gwl, g_wl);

    const int fsm = FLASH_SMEM_FLOATS * (int)sizeof(float);
    cudaFuncSetAttribute(flash_attn, cudaFuncAttributeMaxDynamicSharedMemorySize, fsm);
    cudaFuncSetAttribute(tc_gemm, cudaFuncAttributeMaxDynamicSharedMemorySize, TC_SMEM);

    const int XB = MROWS * DIM / 4 / 256;
    const int WB = DIM * DIM / 4 / 256;

    f32_to_bf16pair<<<XB, 256>>>(x,  gxh, gxl);
    f32_to_bf16pair<<<WB, 256>>>(wq, gwh + 0 * (size_t)DIM * DIM, gwl + 0 * (size_t)DIM * DIM);
    f32_to_bf16pair<<<WB, 256>>>(wk, gwh + 1 * (size_t)DIM * DIM, gwl + 1 * (size_t)DIM * DIM);
    f32_to_bf16pair<<<WB, 256>>>(wv, gwh + 2 * (size_t)DIM * DIM, gwl + 2 * (size_t)DIM * DIM);
    f32_to_bf16pair<<<WB, 256>>>(wo, gwh + 3 * (size_t)DIM * DIM, gwl + 3 * (size_t)DIM * DIM);

    dim3 gg(DIM / 128, MROWS / 128);
    tc_gemm<<<gg, 256, TC_SMEM>>>(gxh, gxl, gwh + 0 * (size_t)DIM * DIM, gwl + 0 * (size_t)DIM * DIM, gq, DIM);
    tc_gemm<<<gg, 256, TC_SMEM>>>(gxh, gxl, gwh + 1 * (size_t)DIM * DIM, gwl + 1 * (size_t)DIM * DIM, gk, DIM);
    tc_gemm<<<gg, 256, TC_SMEM>>>(gxh, gxl, gwh + 2 * (size_t)DIM * DIM, gwl + 2 * (size_t)DIM * DIM, gv, DIM);
    lora_gemm<<<MROWS / 32, 256>>>(x, waq, gqh);
    lora_gemm<<<MROWS / 32, 256>>>(x, wak, gkh);
    rope_kernel<<<MROWS * (DIM / 2) / 256, 256>>>(gq, gk, fcos, fsin);
    flash_attn<<<dim3(SS / FBM, BB * NH), 256, fsm>>>(gq, gk, gv, gqh, gkh, gao);
    f32_to_bf16pair<<<XB, 256>>>(gao, gaoh, gaol);
    tc_gemm<<<gg, 256, TC_SMEM>>>(gaoh, gaol, gwh + 3 * (size_t)DIM * DIM, gwl + 3 * (size_t)DIM * DIM, out, DIM);
}

// round 5
// speedup vs baseline: 2.2471x; 1.4497x over previous
#include <cuda_runtime.h>
#include <cuda_bf16.h>
#include <cstdint>

#define BB 2
#define SS 2048
#define DIM 2048
#define NH 16
#define HD 128
#define RANK 32
#define MROWS (BB*SS)

// -------- scratch (device globals; no allocation allowed) --------
__device__ float g_q [MROWS*DIM];
__device__ float g_k [MROWS*DIM];
__device__ float g_v [MROWS*DIM];
__device__ float g_ao[MROWS*DIM];
__device__ float g_qh[MROWS*RANK];
__device__ float g_kh[MROWS*RANK];
// bf16 hi/lo pairs
__device__ __nv_bfloat16 g_xh [MROWS*DIM];
__device__ __nv_bfloat16 g_xl [MROWS*DIM];
__device__ __nv_bfloat16 g_aoh[MROWS*DIM];
__device__ __nv_bfloat16 g_aol[MROWS*DIM];
__device__ __nv_bfloat16 g_wh [4][DIM*DIM];
__device__ __nv_bfloat16 g_wl [4][DIM*DIM];
// flash operands (bf16 hi/lo)
__device__ __nv_bfloat16 g_qbh[MROWS*DIM];
__device__ __nv_bfloat16 g_qbl[MROWS*DIM];
__device__ __nv_bfloat16 g_kbh[MROWS*DIM];
__device__ __nv_bfloat16 g_kbl[MROWS*DIM];
__device__ __nv_bfloat16 g_vbh[MROWS*DIM];
__device__ __nv_bfloat16 g_vbl[MROWS*DIM];
__device__ __nv_bfloat16 g_qhh[MROWS*RANK];
__device__ __nv_bfloat16 g_qhl[MROWS*RANK];
__device__ __nv_bfloat16 g_khh[MROWS*RANK];
__device__ __nv_bfloat16 g_khl[MROWS*RANK];

__device__ __forceinline__ uint32_t smem_to_u32(const void* smem_ptr) {
    uint32_t addr;
    asm("{ .reg .u64 tmp; cvta.to.shared.u64 tmp, %1; cvt.u32.u64 %0, tmp; }"
        : "=r"(addr) : "l"(smem_ptr));
    return addr;
}

__device__ __forceinline__ void ldsm_x4(uint32_t& d0, uint32_t& d1, uint32_t& d2,
                                        uint32_t& d3, uint32_t addr) {
    asm volatile("ldmatrix.sync.aligned.m8n8.x4.shared.b16 {%0,%1,%2,%3}, [%4];"
                 : "=r"(d0), "=r"(d1), "=r"(d2), "=r"(d3) : "r"(addr));
}
__device__ __forceinline__ void ldsm_x4t(uint32_t& d0, uint32_t& d1, uint32_t& d2,
                                         uint32_t& d3, uint32_t addr) {
    asm volatile("ldmatrix.sync.aligned.m8n8.x4.trans.shared.b16 {%0,%1,%2,%3}, [%4];"
                 : "=r"(d0), "=r"(d1), "=r"(d2), "=r"(d3) : "r"(addr));
}

__device__ __forceinline__ void mma_bf16(float* c, const uint32_t* a,
                                         uint32_t b0, uint32_t b1) {
    asm volatile("mma.sync.aligned.m16n8k16.row.col.f32.bf16.bf16.f32 "
                 "{%0,%1,%2,%3}, {%4,%5,%6,%7}, {%8,%9}, {%0,%1,%2,%3};"
                 : "+f"(c[0]), "+f"(c[1]), "+f"(c[2]), "+f"(c[3])
                 : "r"(a[0]), "r"(a[1]), "r"(a[2]), "r"(a[3]), "r"(b0), "r"(b1));
}

__device__ __forceinline__ void cp16(uint32_t dst, const void* src) {
    asm volatile("cp.async.cg.shared.global [%0], [%1], 16;" :: "r"(dst), "l"(src));
}

__device__ __forceinline__ void split2(float x, float y, uint32_t& hi, uint32_t& lo) {
    __nv_bfloat16 hx = __float2bfloat16(x), hy = __float2bfloat16(y);
    float rx = x - __bfloat162float(hx), ry = y - __bfloat162float(hy);
    __nv_bfloat162 H; H.x = hx; H.y = hy;
    __nv_bfloat162 L; L.x = __float2bfloat16(rx); L.y = __float2bfloat16(ry);
    hi = *(uint32_t*)&H; lo = *(uint32_t*)&L;
}

// ============================================================
// fp32 -> (bf16 hi, bf16 lo) conversion, vectorized x4
// ============================================================
__global__ __launch_bounds__(256) void f32_to_bf16pair(const float* __restrict__ in,
                                                       __nv_bfloat16* __restrict__ hi,
                                                       __nv_bfloat16* __restrict__ lo) {
    int i = blockIdx.x * 256 + threadIdx.x;
    float4 v = ((const float4*)in)[i];
    __nv_bfloat162 h0, h1, l0, l1;
    h0.x = __float2bfloat16(v.x); h0.y = __float2bfloat16(v.y);
    h1.x = __float2bfloat16(v.z); h1.y = __float2bfloat16(v.w);
    l0.x = __float2bfloat16(v.x - __bfloat162float(h0.x));
    l0.y = __float2bfloat16(v.y - __bfloat162float(h0.y));
    l1.x = __float2bfloat16(v.z - __bfloat162float(h1.x));
    l1.y = __float2bfloat16(v.w - __bfloat162float(h1.y));
    ((__nv_bfloat162*)hi)[2 * i]     = h0;
    ((__nv_bfloat162*)hi)[2 * i + 1] = h1;
    ((__nv_bfloat162*)lo)[2 * i]     = l0;
    ((__nv_bfloat162*)lo)[2 * i + 1] = l1;
}

// ============================================================
// mma.sync GEMM (same as R3): C = (Ahi+Alo)(Bhi+Blo)^T
// ============================================================
#define KDIM 2048
#define TBK 32
#define NKIT (KDIM / TBK)
#define LDK 40
#define TILE_B (128 * LDK * 2)
#define STAGE_B (4 * TILE_B)
#define TC_SMEM (2 * STAGE_B)

__global__ __launch_bounds__(256) void tc_gemm(const __nv_bfloat16* __restrict__ Ahi,
                                               const __nv_bfloat16* __restrict__ Alo,
                                               const __nv_bfloat16* __restrict__ Bhi,
                                               const __nv_bfloat16* __restrict__ Blo,
                                               float* __restrict__ C, int N) {
    extern __shared__ char smem[];
    const uint32_t sb = smem_to_u32(smem);
    const int tid = threadIdx.x;
    const int wid = tid >> 5, lane = tid & 31;
    const int m0 = blockIdx.y * 128;
    const int n0 = blockIdx.x * 128;
    const int wm = (wid & 3) * 32;
    const int wn = (wid >> 2) * 64;

    const __nv_bfloat16* srcs[4] = {
        Ahi + (size_t)m0 * KDIM, Alo + (size_t)m0 * KDIM,
        Bhi + (size_t)n0 * KDIM, Blo + (size_t)n0 * KDIM };

    int l_tile[8], l_r[8], l_c[8];
#pragma unroll
    for (int u = 0; u < 8; u++) {
        int cid = u * 256 + tid;
        l_tile[u] = cid >> 9;
        int w = cid & 511;
        l_r[u] = w >> 2;
        l_c[u] = w & 3;
    }

    auto issue_stage = [&](int it, int stage) {
        uint32_t base = sb + stage * STAGE_B;
        int k0 = it * TBK;
#pragma unroll
        for (int u = 0; u < 8; u++) {
            uint32_t dst = base + l_tile[u] * TILE_B + l_r[u] * (LDK * 2) + l_c[u] * 16;
            const __nv_bfloat16* src = srcs[l_tile[u]] + (size_t)l_r[u] * KDIM + k0 + l_c[u] * 8;
            cp16(dst, src);
        }
        asm volatile("cp.async.commit_group;" ::: "memory");
    };

    float acc[2][8][4];
#pragma unroll
    for (int i = 0; i < 2; i++)
#pragma unroll
        for (int j = 0; j < 8; j++)
#pragma unroll
            for (int q = 0; q < 4; q++) acc[i][j][q] = 0.f;

    const int lrow = lane & 15;
    const int lcol = (lane >> 4) * 8;

    issue_stage(0, 0);

    for (int it = 0; it < NKIT; it++) {
        int cur = it & 1;
        if (it + 1 < NKIT) {
            issue_stage(it + 1, cur ^ 1);
            asm volatile("cp.async.wait_group 1;" ::: "memory");
        } else {
            asm volatile("cp.async.wait_group 0;" ::: "memory");
        }
        __syncthreads();

        uint32_t base = sb + cur * STAGE_B;
        uint32_t aA_hi = base + 0 * TILE_B;
        uint32_t aA_lo = base + 1 * TILE_B;
        uint32_t aB_hi = base + 2 * TILE_B;
        uint32_t aB_lo = base + 3 * TILE_B;

#pragma unroll
        for (int ks = 0; ks < 2; ks++) {
            const int kc = ks * 16 + lcol;
            uint32_t ah[2][4], al[2][4], bh[4][4], bl[4][4];
#pragma unroll
            for (int ma = 0; ma < 2; ma++) {
                uint32_t off = (wm + ma * 16 + lrow) * (LDK * 2) + kc * 2;
                ldsm_x4(ah[ma][0], ah[ma][1], ah[ma][2], ah[ma][3], aA_hi + off);
                ldsm_x4(al[ma][0], al[ma][1], al[ma][2], al[ma][3], aA_lo + off);
            }
#pragma unroll
            for (int nb = 0; nb < 4; nb++) {
                uint32_t off = (wn + nb * 16 + lrow) * (LDK * 2) + kc * 2;
                ldsm_x4(bh[nb][0], bh[nb][1], bh[nb][2], bh[nb][3], aB_hi + off);
                ldsm_x4(bl[nb][0], bl[nb][1], bl[nb][2], bl[nb][3], aB_lo + off);
            }
#pragma unroll
            for (int ma = 0; ma < 2; ma++)
#pragma unroll
                for (int nb = 0; nb < 4; nb++) {
                    mma_bf16(acc[ma][nb * 2],     ah[ma], bh[nb][0], bh[nb][2]);
                    mma_bf16(acc[ma][nb * 2 + 1], ah[ma], bh[nb][1], bh[nb][3]);
                    mma_bf16(acc[ma][nb * 2],     ah[ma], bl[nb][0], bl[nb][2]);
                    mma_bf16(acc[ma][nb * 2 + 1], ah[ma], bl[nb][1], bl[nb][3]);
                    mma_bf16(acc[ma][nb * 2],     al[ma], bh[nb][0], bh[nb][2]);
                    mma_bf16(acc[ma][nb * 2 + 1], al[ma], bh[nb][1], bh[nb][3]);
                }
        }
        __syncthreads();
    }

    const int er = lane >> 2;
    const int ec = (lane & 3) * 2;
#pragma unroll
    for (int ma = 0; ma < 2; ma++) {
#pragma unroll
        for (int na = 0; na < 8; na++) {
            int row = m0 + wm + ma * 16 + er;
            int col = n0 + wn + na * 8 + ec;
            float* p0 = C + (size_t)row * N + col;
            float* p1 = C + (size_t)(row + 8) * N + col;
            p0[0] = acc[ma][na][0]; p0[1] = acc[ma][na][1];
            p1[0] = acc[ma][na][2]; p1[1] = acc[ma][na][3];
        }
    }
}

// ============================================================
// LoRA projection (fp32 SIMT)
// ============================================================
__global__ __launch_bounds__(256) void lora_gemm(const float* __restrict__ X,
                                                 const float* __restrict__ W,
                                                 float* __restrict__ C) {
    __shared__ float xs[32][33];
    __shared__ float ws[32][33];
    const int tid = threadIdx.x;
    const int lane = tid & 31, wrp = tid >> 5;
    const int m0 = blockIdx.x * 32;
    float acc[4] = {0.f, 0.f, 0.f, 0.f};

    for (int k0 = 0; k0 < DIM; k0 += 32) {
        __syncthreads();
#pragma unroll
        for (int l = 0; l < 4; l++) {
            int lin = l * 256 + tid;
            int r = lin >> 5, c = lin & 31;
            xs[r][c] = X[(size_t)(m0 + r) * DIM + k0 + c];
            ws[r][c] = W[(size_t)r * DIM + k0 + c];
        }
        __syncthreads();
#pragma unroll
        for (int kk = 0; kk < 32; kk++) {
            float wv = ws[lane][kk];
#pragma unroll
            for (int i = 0; i < 4; i++)
                acc[i] = fmaf(xs[wrp * 4 + i][kk], wv, acc[i]);
        }
    }
#pragma unroll
    for (int i = 0; i < 4; i++)
        C[(size_t)(m0 + wrp * 4 + i) * RANK + lane] = acc[i];
}

// ============================================================
// RoPE + bf16 hi/lo split (reads fp32 q/k, writes 4 bf16 arrays)
// ============================================================
__global__ __launch_bounds__(256) void rope_bf16(const float* __restrict__ q,
                                                 const float* __restrict__ k,
                                                 const float* __restrict__ cs,
                                                 const float* __restrict__ sn,
                                                 __nv_bfloat16* __restrict__ qh,
                                                 __nv_bfloat16* __restrict__ ql,
                                                 __nv_bfloat16* __restrict__ kh,
                                                 __nv_bfloat16* __restrict__ kl) {
    int t = blockIdx.x * 256 + threadIdx.x;
    int p = t & 63;
    int row = t / (DIM / 2);
    int sidx = row & (SS - 1);
    float c = cs[sidx * 64 + p];
    float si = sn[sidx * 64 + p];

    float2 v = ((const float2*)q)[t];
    float ox = v.x * c - v.y * si;
    float oy = v.x * si + v.y * c;
    __nv_bfloat162 H, L;
    H.x = __float2bfloat16(ox); H.y = __float2bfloat16(oy);
    L.x = __float2bfloat16(ox - __bfloat162float(H.x));
    L.y = __float2bfloat16(oy - __bfloat162float(H.y));
    ((__nv_bfloat162*)qh)[t] = H;
    ((__nv_bfloat162*)ql)[t] = L;

    float2 w = ((const float2*)k)[t];
    float wx = w.x * c - w.y * si;
    float wy = w.x * si + w.y * c;
    H.x = __float2bfloat16(wx); H.y = __float2bfloat16(wy);
    L.x = __float2bfloat16(wx - __bfloat162float(H.x));
    L.y = __float2bfloat16(wy - __bfloat162float(H.y));
    ((__nv_bfloat162*)kh)[t] = H;
    ((__nv_bfloat162*)kl)[t] = L;
}

// ============================================================
// Tensor-core flash attention with adaptive sigmoid gate.
// BM=128 (8 warps x 16 rows), BN=64, HD=128, hi/lo bf16 everywhere.
// ============================================================
#define SQB 272   // smem row stride bytes for 128-wide tiles (136 halves)
#define SRB 80    // smem row stride bytes for rank tiles (40 halves)
#define FSMEM 169984

__global__ __launch_bounds__(256) void flash_tc(
    const __nv_bfloat16* __restrict__ Qh_, const __nv_bfloat16* __restrict__ Ql_,
    const __nv_bfloat16* __restrict__ Kh_, const __nv_bfloat16* __restrict__ Kl_,
    const __nv_bfloat16* __restrict__ Vh_, const __nv_bfloat16* __restrict__ Vl_,
    const __nv_bfloat16* __restrict__ QHh_, const __nv_bfloat16* __restrict__ QHl_,
    const __nv_bfloat16* __restrict__ KHh_, const __nv_bfloat16* __restrict__ KHl_,
    float* __restrict__ O) {
    extern __shared__ char sm[];
    const uint32_t sb = smem_to_u32(sm);
    const uint32_t oQh = 0, oQl = 34816, oKh = 69632, oKl = 87040,
                   oVh = 104448, oVl = 121856, oqh = 139264, oql = 149504,
                   okh = 159744, okl = 164864;
    const int tid = threadIdx.x, lane = tid & 31, wid = tid >> 5;
    const int qt = gridDim.x - 1 - blockIdx.x;   // heavy tiles first
    const int b = blockIdx.y >> 4, h = blockIdx.y & 15;
    const int q0 = qt * 128;
    const size_t rowbase = (size_t)b * SS;
    const int wm = wid * 16;
    const int lrow = lane & 15, lcol = (lane >> 4) * 8;
    const float SC = 0.08838834764831845f;

    // ---- Q + qh loads (async) ----
    {
        const __nv_bfloat16* qsrc[2] = { Qh_, Ql_ };
        const uint32_t qoff[2] = { oQh, oQl };
#pragma unroll
        for (int buf = 0; buf < 2; buf++)
#pragma unroll
            for (int u = 0; u < 8; u++) {
                int cid = u * 256 + tid;           // 0..2047
                int row = cid >> 4, col = cid & 15;
                cp16(sb + qoff[buf] + row * SQB + col * 16,
                     qsrc[buf] + (rowbase + q0 + row) * DIM + h * HD + col * 8);
            }
        const __nv_bfloat16* hsrc[2] = { QHh_, QHl_ };
        const uint32_t hoff[2] = { oqh, oql };
#pragma unroll
        for (int buf = 0; buf < 2; buf++)
#pragma unroll
            for (int u = 0; u < 2; u++) {
                int cid = u * 256 + tid;           // 0..511
                int row = cid >> 2, col = cid & 3;
                cp16(sb + hoff[buf] + row * SRB + col * 16,
                     hsrc[buf] + (rowbase + q0 + row) * RANK + col * 8);
            }
        asm volatile("cp.async.commit_group;" ::: "memory");
    }

    float o[16][4];
#pragma unroll
    for (int i = 0; i < 16; i++)
#pragma unroll
        for (int e = 0; e < 4; e++) o[i][e] = 0.f;
    float m0 = -1e30f, m1 = -1e30f, l0 = 0.f, l1 = 0.f;

    const int nkt = q0 / 64 + 2;
    for (int kt = 0; kt < nkt; kt++) {
        const int k0 = kt * 64;
        __syncthreads();   // all warps done reading previous K/V
        {
            const __nv_bfloat16* ksrc[4] = { Kh_, Kl_, Vh_, Vl_ };
            const uint32_t koff[4] = { oKh, oKl, oVh, oVl };
#pragma unroll
            for (int buf = 0; buf < 4; buf++)
#pragma unroll
                for (int u = 0; u < 4; u++) {
                    int cid = u * 256 + tid;       // 0..1023
                    int row = cid >> 4, col = cid & 15;
                    cp16(sb + koff[buf] + row * SQB + col * 16,
                         ksrc[buf] + (rowbase + k0 + row) * DIM + h * HD + col * 8);
                }
            const __nv_bfloat16* hsrc[2] = { KHh_, KHl_ };
            const uint32_t hoff[2] = { okh, okl };
#pragma unroll
            for (int buf = 0; buf < 2; buf++) {
                int cid = tid;                     // 0..255
                int row = cid >> 2, col = cid & 3;
                cp16(sb + hoff[buf] + row * SRB + col * 16,
                     hsrc[buf] + (rowbase + k0 + row) * RANK + col * 8);
            }
            asm volatile("cp.async.commit_group;" ::: "memory");
            asm volatile("cp.async.wait_group 0;" ::: "memory");
        }
        __syncthreads();

        const bool fullskip = (k0 > q0 + wm + 15);
        if (fullskip) continue;

        // ---- gate logits G (rank 32, hi/lo) -> sigmoid ----
        float gg[8][4];
#pragma unroll
        for (int i = 0; i < 8; i++)
#pragma unroll
            for (int e = 0; e < 4; e++) gg[i][e] = 0.f;
#pragma unroll
        for (int ks = 0; ks < 2; ks++) {
            const int kc = ks * 16 + lcol;
            uint32_t ah[4], al[4];
            ldsm_x4(ah[0], ah[1], ah[2], ah[3], sb + oqh + (wm + lrow) * SRB + kc * 2);
            ldsm_x4(al[0], al[1], al[2], al[3], sb + oql + (wm + lrow) * SRB + kc * 2);
#pragma unroll
            for (int nb = 0; nb < 4; nb++) {
                uint32_t bh[4], bl[4];
                uint32_t boff = (nb * 16 + lrow) * SRB + kc * 2;
                ldsm_x4(bh[0], bh[1], bh[2], bh[3], sb + okh + boff);
                ldsm_x4(bl[0], bl[1], bl[2], bl[3], sb + okl + boff);
                mma_bf16(gg[nb * 2],     ah, bh[0], bh[2]);
                mma_bf16(gg[nb * 2],     ah, bl[0], bl[2]);
                mma_bf16(gg[nb * 2],     al, bh[0], bh[2]);
                mma_bf16(gg[nb * 2 + 1], ah, bh[1], bh[3]);
                mma_bf16(gg[nb * 2 + 1], ah, bl[1], bl[3]);
                mma_bf16(gg[nb * 2 + 1], al, bh[1], bh[3]);
            }
        }
#pragma unroll
        for (int i = 0; i < 8; i++)
#pragma unroll
            for (int e = 0; e < 4; e++)
                gg[i][e] = 1.f / (1.f + __expf(-gg[i][e]));

        // ---- S = Q.K^T (hi/lo) ----
        float s[8][4];
#pragma unroll
        for (int i = 0; i < 8; i++)
#pragma unroll
            for (int e = 0; e < 4; e++) s[i][e] = 0.f;
#pragma unroll
        for (int ks = 0; ks < 8; ks++) {
            const int kc = ks * 16 + lcol;
            uint32_t ah[4], al[4];
            ldsm_x4(ah[0], ah[1], ah[2], ah[3], sb + oQh + (wm + lrow) * SQB + kc * 2);
            ldsm_x4(al[0], al[1], al[2], al[3], sb + oQl + (wm + lrow) * SQB + kc * 2);
#pragma unroll
            for (int nb = 0; nb < 4; nb++) {
                uint32_t bh[4], bl[4];
                uint32_t boff = (nb * 16 + lrow) * SQB + kc * 2;
                ldsm_x4(bh[0], bh[1], bh[2], bh[3], sb + oKh + boff);
                ldsm_x4(bl[0], bl[1], bl[2], bl[3], sb + oKl + boff);
                mma_bf16(s[nb * 2],     ah, bh[0], bh[2]);
                mma_bf16(s[nb * 2],     ah, bl[0], bl[2]);
                mma_bf16(s[nb * 2],     al, bh[0], bh[2]);
                mma_bf16(s[nb * 2 + 1], ah, bh[1], bh[3]);
                mma_bf16(s[nb * 2 + 1], ah, bl[1], bl[3]);
                mma_bf16(s[nb * 2 + 1], al, bh[1], bh[3]);
            }
        }

        // ---- scale + causal mask ----
        const int r0g = q0 + wm + (lane >> 2);
        if (k0 + 64 > q0 + wm) {
#pragma unroll
            for (int na = 0; na < 8; na++)
#pragma unroll
                for (int e = 0; e < 4; e++) {
                    int key = k0 + na * 8 + (lane & 3) * 2 + (e & 1);
                    int row = r0g + (e >> 1) * 8;
                    s[na][e] = (key <= row) ? s[na][e] * SC : -1e30f;
                }
        } else {
#pragma unroll
            for (int na = 0; na < 8; na++)
#pragma unroll
                for (int e = 0; e < 4; e++) s[na][e] *= SC;
        }

        // ---- online softmax (rows r and r+8) ----
        float mx0 = -1e30f, mx1 = -1e30f;
#pragma unroll
        for (int na = 0; na < 8; na++) {
            mx0 = fmaxf(mx0, fmaxf(s[na][0], s[na][1]));
            mx1 = fmaxf(mx1, fmaxf(s[na][2], s[na][3]));
        }
        mx0 = fmaxf(mx0, __shfl_xor_sync(0xffffffffu, mx0, 1));
        mx0 = fmaxf(mx0, __shfl_xor_sync(0xffffffffu, mx0, 2));
        mx1 = fmaxf(mx1, __shfl_xor_sync(0xffffffffu, mx1, 1));
        mx1 = fmaxf(mx1, __shfl_xor_sync(0xffffffffu, mx1, 2));
        float mn0 = fmaxf(m0, mx0), mn1 = fmaxf(m1, mx1);
        float al0 = __expf(m0 - mn0), al1 = __expf(m1 - mn1);
        m0 = mn0; m1 = mn1;
        float rs0 = 0.f, rs1 = 0.f;
#pragma unroll
        for (int na = 0; na < 8; na++) {
            s[na][0] = __expf(s[na][0] - m0); rs0 += s[na][0];
            s[na][1] = __expf(s[na][1] - m0); rs0 += s[na][1];
            s[na][2] = __expf(s[na][2] - m1); rs1 += s[na][2];
            s[na][3] = __expf(s[na][3] - m1); rs1 += s[na][3];
        }
        rs0 += __shfl_xor_sync(0xffffffffu, rs0, 1);
        rs0 += __shfl_xor_sync(0xffffffffu, rs0, 2);
        rs1 += __shfl_xor_sync(0xffffffffu, rs1, 1);
        rs1 += __shfl_xor_sync(0xffffffffu, rs1, 2);
        l0 = l0 * al0 + rs0;
        l1 = l1 * al1 + rs1;
#pragma unroll
        for (int na = 0; na < 16; na++) {
            o[na][0] *= al0; o[na][1] *= al0;
            o[na][2] *= al1; o[na][3] *= al1;
        }
        // gate the numerator
#pragma unroll
        for (int na = 0; na < 8; na++)
#pragma unroll
            for (int e = 0; e < 4; e++) s[na][e] *= gg[na][e];

        // ---- O += W.V (hi/lo), W from registers ----
#pragma unroll
        for (int j = 0; j < 4; j++) {
            uint32_t wa[4], wl[4];
            split2(s[2 * j][0],     s[2 * j][1],     wa[0], wl[0]);
            split2(s[2 * j][2],     s[2 * j][3],     wa[1], wl[1]);
            split2(s[2 * j + 1][0], s[2 * j + 1][1], wa[2], wl[2]);
            split2(s[2 * j + 1][2], s[2 * j + 1][3], wa[3], wl[3]);
#pragma unroll
            for (int dp = 0; dp < 8; dp++) {
                uint32_t vh[4], vl[4];
                uint32_t voff = (j * 16 + lrow) * SQB + (dp * 16 + lcol) * 2;
                ldsm_x4t(vh[0], vh[1], vh[2], vh[3], sb + oVh + voff);
                ldsm_x4t(vl[0], vl[1], vl[2], vl[3], sb + oVl + voff);
                mma_bf16(o[dp * 2],     wa, vh[0], vh[1]);
                mma_bf16(o[dp * 2],     wa, vl[0], vl[1]);
                mma_bf16(o[dp * 2],     wl, vh[0], vh[1]);
                mma_bf16(o[dp * 2 + 1], wa, vh[2], vh[3]);
                mma_bf16(o[dp * 2 + 1], wa, vl[2], vl[3]);
                mma_bf16(o[dp * 2 + 1], wl, vh[2], vh[3]);
            }
        }
    }

    // ---- epilogue ----
    const float inv0 = 1.f / l0, inv1 = 1.f / l1;
    const int row0 = q0 + wm + (lane >> 2);
    float* p0 = O + (rowbase + row0) * DIM + h * HD;
    float* p1 = p0 + 8 * DIM;
#pragma unroll
    for (int na = 0; na < 16; na++) {
        int d = na * 8 + (lane & 3) * 2;
        *(float2*)(p0 + d) = make_float2(o[na][0] * inv0, o[na][1] * inv0);
        *(float2*)(p1 + d) = make_float2(o[na][2] * inv1, o[na][3] * inv1);
    }
}

// ============================================================
// launch
// ============================================================
extern "C" void kernel_launch(void* const* d_in, const int* in_sizes, int n_in,
                              void* d_out, int out_size) {
    const float* x    = (const float*)d_in[0];
    const float* fcos = (const float*)d_in[2];
    const float* fsin = (const float*)d_in[3];
    const float* wq   = (const float*)d_in[4];
    const float* wk   = (const float*)d_in[5];
    const float* wv   = (const float*)d_in[6];
    const float* wo   = (const float*)d_in[7];
    const float* waq  = (const float*)d_in[8];
    const float* wak  = (const float*)d_in[9];
    float* out = (float*)d_out;

    float *gq, *gk, *gv, *gao, *gqh, *gkh;
    __nv_bfloat16 *gxh, *gxl, *gaoh, *gaol, *gwh, *gwl;
    __nv_bfloat16 *qbh, *qbl, *kbh, *kbl, *vbh, *vbl, *qhh, *qhl, *khh, *khl;
    cudaGetSymbolAddress((void**)&gq,  g_q);
    cudaGetSymbolAddress((void**)&gk,  g_k);
    cudaGetSymbolAddress((void**)&gv,  g_v);
    cudaGetSymbolAddress((void**)&gao, g_ao);
    cudaGetSymbolAddress((void**)&gqh, g_qh);
    cudaGetSymbolAddress((void**)&gkh, g_kh);
    cudaGetSymbolAddress((void**)&gxh, g_xh);
    cudaGetSymbolAddress((void**)&gxl, g_xl);
    cudaGetSymbolAddress((void**)&gaoh, g_aoh);
    cudaGetSymbolAddress((void**)&gaol, g_aol);
    cudaGetSymbolAddress((void**)&gwh, g_wh);
    cudaGetSymbolAddress((void**)&gwl, g_wl);
    cudaGetSymbolAddress((void**)&qbh, g_qbh);
    cudaGetSymbolAddress((void**)&qbl, g_qbl);
    cudaGetSymbolAddress((void**)&kbh, g_kbh);
    cudaGetSymbolAddress((void**)&kbl, g_kbl);
    cudaGetSymbolAddress((void**)&vbh, g_vbh);
    cudaGetSymbolAddress((void**)&vbl, g_vbl);
    cudaGetSymbolAddress((void**)&qhh, g_qhh);
    cudaGetSymbolAddress((void**)&qhl, g_qhl);
    cudaGetSymbolAddress((void**)&khh, g_khh);
    cudaGetSymbolAddress((void**)&khl, g_khl);

    cudaFuncSetAttribute(tc_gemm, cudaFuncAttributeMaxDynamicSharedMemorySize, TC_SMEM);
    cudaFuncSetAttribute(flash_tc, cudaFuncAttributeMaxDynamicSharedMemorySize, FSMEM);

    const int XB = MROWS * DIM / 4 / 256;
    const int WB = DIM * DIM / 4 / 256;
    const int RB = MROWS * RANK / 4 / 256;

    f32_to_bf16pair<<<XB, 256>>>(x,  gxh, gxl);
    f32_to_bf16pair<<<WB, 256>>>(wq, gwh + 0 * (size_t)DIM * DIM, gwl + 0 * (size_t)DIM * DIM);
    f32_to_bf16pair<<<WB, 256>>>(wk, gwh + 1 * (size_t)DIM * DIM, gwl + 1 * (size_t)DIM * DIM);
    f32_to_bf16pair<<<WB, 256>>>(wv, gwh + 2 * (size_t)DIM * DIM, gwl + 2 * (size_t)DIM * DIM);
    f32_to_bf16pair<<<WB, 256>>>(wo, gwh + 3 * (size_t)DIM * DIM, gwl + 3 * (size_t)DIM * DIM);

    dim3 gg(DIM / 128, MROWS / 128);
    tc_gemm<<<gg, 256, TC_SMEM>>>(gxh, gxl, gwh + 0 * (size_t)DIM * DIM, gwl + 0 * (size_t)DIM * DIM, gq, DIM);
    tc_gemm<<<gg, 256, TC_SMEM>>>(gxh, gxl, gwh + 1 * (size_t)DIM * DIM, gwl + 1 * (size_t)DIM * DIM, gk, DIM);
    tc_gemm<<<gg, 256, TC_SMEM>>>(gxh, gxl, gwh + 2 * (size_t)DIM * DIM, gwl + 2 * (size_t)DIM * DIM, gv, DIM);
    lora_gemm<<<MROWS / 32, 256>>>(x, waq, gqh);
    lora_gemm<<<MROWS / 32, 256>>>(x, wak, gkh);

    rope_bf16<<<MROWS * (DIM / 2) / 256, 256>>>(gq, gk, fcos, fsin, qbh, qbl, kbh, kbl);
    f32_to_bf16pair<<<XB, 256>>>(gv, vbh, vbl);
    f32_to_bf16pair<<<RB, 256>>>(gqh, qhh, qhl);
    f32_to_bf16pair<<<RB, 256>>>(gkh, khh, khl);

    flash_tc<<<dim3(SS / 128, BB * NH), 256, FSMEM>>>(qbh, qbl, kbh, kbl, vbh, vbl,
                                                      qhh, qhl, khh, khl, gao);

    f32_to_bf16pair<<<XB, 256>>>(gao, gaoh, gaol);
    tc_gemm<<<gg, 256, TC_SMEM>>>(gaoh, gaol, gwh + 3 * (size_t)DIM * DIM, gwl + 3 * (size_t)DIM * DIM, out, DIM);
}

// round 8
// speedup vs baseline: 2.2970x; 1.0222x over previous
#include <cuda_runtime.h>
#include <cuda_bf16.h>
#include <cstdint>

#define BB 2
#define SS 2048
#define DIM 2048
#define NH 16
#define HD 128
#define RANK 32
#define MROWS (BB*SS)

// -------- scratch (device globals; no allocation allowed) --------
__device__ __nv_bfloat16 g_xh [MROWS*DIM];
__device__ __nv_bfloat16 g_xl [MROWS*DIM];
__device__ __nv_bfloat16 g_aoh[MROWS*DIM];
__device__ __nv_bfloat16 g_aol[MROWS*DIM];
__device__ __nv_bfloat16 g_wh [4][DIM*DIM];
__device__ __nv_bfloat16 g_wl [4][DIM*DIM];
__device__ __nv_bfloat16 g_qbh[MROWS*DIM];
__device__ __nv_bfloat16 g_qbl[MROWS*DIM];
__device__ __nv_bfloat16 g_kbh[MROWS*DIM];
__device__ __nv_bfloat16 g_kbl[MROWS*DIM];
__device__ __nv_bfloat16 g_vbh[MROWS*DIM];
__device__ __nv_bfloat16 g_vbl[MROWS*DIM];
__device__ __nv_bfloat16 g_qhh[MROWS*RANK];
__device__ __nv_bfloat16 g_qhl[MROWS*RANK];
__device__ __nv_bfloat16 g_khh[MROWS*RANK];
__device__ __nv_bfloat16 g_khl[MROWS*RANK];

__device__ __forceinline__ uint32_t smem_to_u32(const void* smem_ptr) {
    uint32_t addr;
    asm("{ .reg .u64 tmp; cvta.to.shared.u64 tmp, %1; cvt.u32.u64 %0, tmp; }"
        : "=r"(addr) : "l"(smem_ptr));
    return addr;
}

__device__ __forceinline__ void ldsm_x4(uint32_t& d0, uint32_t& d1, uint32_t& d2,
                                        uint32_t& d3, uint32_t addr) {
    asm volatile("ldmatrix.sync.aligned.m8n8.x4.shared.b16 {%0,%1,%2,%3}, [%4];"
                 : "=r"(d0), "=r"(d1), "=r"(d2), "=r"(d3) : "r"(addr));
}
__device__ __forceinline__ void ldsm_x4t(uint32_t& d0, uint32_t& d1, uint32_t& d2,
                                         uint32_t& d3, uint32_t addr) {
    asm volatile("ldmatrix.sync.aligned.m8n8.x4.trans.shared.b16 {%0,%1,%2,%3}, [%4];"
                 : "=r"(d0), "=r"(d1), "=r"(d2), "=r"(d3) : "r"(addr));
}

__device__ __forceinline__ void mma_bf16(float* c, const uint32_t* a,
                                         uint32_t b0, uint32_t b1) {
    asm volatile("mma.sync.aligned.m16n8k16.row.col.f32.bf16.bf16.f32 "
                 "{%0,%1,%2,%3}, {%4,%5,%6,%7}, {%8,%9}, {%0,%1,%2,%3};"
                 : "+f"(c[0]), "+f"(c[1]), "+f"(c[2]), "+f"(c[3])
                 : "r"(a[0]), "r"(a[1]), "r"(a[2]), "r"(a[3]), "r"(b0), "r"(b1));
}

__device__ __forceinline__ void cp16(uint32_t dst, const void* src) {
    asm volatile("cp.async.cg.shared.global [%0], [%1], 16;" :: "r"(dst), "l"(src));
}
#define CP_COMMIT()  asm volatile("cp.async.commit_group;" ::: "memory")
#define CP_WAIT(n)   asm volatile("cp.async.wait_group %0;" :: "n"(n) : "memory")

__device__ __forceinline__ void split2(float x, float y, uint32_t& hi, uint32_t& lo) {
    __nv_bfloat16 hx = __float2bfloat16(x), hy = __float2bfloat16(y);
    float rx = x - __bfloat162float(hx), ry = y - __bfloat162float(hy);
    __nv_bfloat162 H; H.x = hx; H.y = hy;
    __nv_bfloat162 L; L.x = __float2bfloat16(rx); L.y = __float2bfloat16(ry);
    hi = *(uint32_t*)&H; lo = *(uint32_t*)&L;
}

// ============================================================
// fp32 -> (bf16 hi, bf16 lo)
// ============================================================
__global__ __launch_bounds__(256) void f32_to_bf16pair(const float* __restrict__ in,
                                                       __nv_bfloat16* __restrict__ hi,
                                                       __nv_bfloat16* __restrict__ lo) {
    int i = blockIdx.x * 256 + threadIdx.x;
    float4 v = ((const float4*)in)[i];
    __nv_bfloat162 h0, h1, l0, l1;
    h0.x = __float2bfloat16(v.x); h0.y = __float2bfloat16(v.y);
    h1.x = __float2bfloat16(v.z); h1.y = __float2bfloat16(v.w);
    l0.x = __float2bfloat16(v.x - __bfloat162float(h0.x));
    l0.y = __float2bfloat16(v.y - __bfloat162float(h0.y));
    l1.x = __float2bfloat16(v.z - __bfloat162float(h1.x));
    l1.y = __float2bfloat16(v.w - __bfloat162float(h1.y));
    ((__nv_bfloat162*)hi)[2 * i]     = h0;
    ((__nv_bfloat162*)hi)[2 * i + 1] = h1;
    ((__nv_bfloat162*)lo)[2 * i]     = l0;
    ((__nv_bfloat162*)lo)[2 * i + 1] = l1;
}

// ============================================================
// mma.sync GEMM: C = (Ahi+Alo)(Bhi+Blo)^T, dual-mode epilogue
// (f32 out  OR  bf16 hi/lo pair out)
// ============================================================
#define KDIM 2048
#define TBK 32
#define NKIT (KDIM / TBK)
#define LDK 40
#define TILE_B (128 * LDK * 2)
#define STAGE_B (4 * TILE_B)
#define TC_SMEM (2 * STAGE_B)

__global__ __launch_bounds__(256) void tc_gemm(const __nv_bfloat16* __restrict__ Ahi,
                                               const __nv_bfloat16* __restrict__ Alo,
                                               const __nv_bfloat16* __restrict__ Bhi,
                                               const __nv_bfloat16* __restrict__ Blo,
                                               float* __restrict__ C,
                                               __nv_bfloat16* __restrict__ Chi,
                                               __nv_bfloat16* __restrict__ Clo,
                                               int N) {
    extern __shared__ char smem[];
    const uint32_t sb = smem_to_u32(smem);
    const int tid = threadIdx.x;
    const int wid = tid >> 5, lane = tid & 31;
    const int m0 = blockIdx.y * 128;
    const int n0 = blockIdx.x * 128;
    const int wm = (wid & 3) * 32;
    const int wn = (wid >> 2) * 64;

    const __nv_bfloat16* srcs[4] = {
        Ahi + (size_t)m0 * KDIM, Alo + (size_t)m0 * KDIM,
        Bhi + (size_t)n0 * KDIM, Blo + (size_t)n0 * KDIM };

    int l_tile[8], l_r[8], l_c[8];
#pragma unroll
    for (int u = 0; u < 8; u++) {
        int cid = u * 256 + tid;
        l_tile[u] = cid >> 9;
        int w = cid & 511;
        l_r[u] = w >> 2;
        l_c[u] = w & 3;
    }

    auto issue_stage = [&](int it, int stage) {
        uint32_t base = sb + stage * STAGE_B;
        int k0 = it * TBK;
#pragma unroll
        for (int u = 0; u < 8; u++) {
            uint32_t dst = base + l_tile[u] * TILE_B + l_r[u] * (LDK * 2) + l_c[u] * 16;
            const __nv_bfloat16* src = srcs[l_tile[u]] + (size_t)l_r[u] * KDIM + k0 + l_c[u] * 8;
            cp16(dst, src);
        }
        CP_COMMIT();
    };

    float acc[2][8][4];
#pragma unroll
    for (int i = 0; i < 2; i++)
#pragma unroll
        for (int j = 0; j < 8; j++)
#pragma unroll
            for (int q = 0; q < 4; q++) acc[i][j][q] = 0.f;

    const int lrow = lane & 15;
    const int lcol = (lane >> 4) * 8;

    issue_stage(0, 0);

    for (int it = 0; it < NKIT; it++) {
        int cur = it & 1;
        if (it + 1 < NKIT) {
            issue_stage(it + 1, cur ^ 1);
            CP_WAIT(1);
        } else {
            CP_WAIT(0);
        }
        __syncthreads();

        uint32_t base = sb + cur * STAGE_B;
        uint32_t aA_hi = base + 0 * TILE_B;
        uint32_t aA_lo = base + 1 * TILE_B;
        uint32_t aB_hi = base + 2 * TILE_B;
        uint32_t aB_lo = base + 3 * TILE_B;

#pragma unroll
        for (int ks = 0; ks < 2; ks++) {
            const int kc = ks * 16 + lcol;
            uint32_t ah[2][4], al[2][4], bh[4][4], bl[4][4];
#pragma unroll
            for (int ma = 0; ma < 2; ma++) {
                uint32_t off = (wm + ma * 16 + lrow) * (LDK * 2) + kc * 2;
                ldsm_x4(ah[ma][0], ah[ma][1], ah[ma][2], ah[ma][3], aA_hi + off);
                ldsm_x4(al[ma][0], al[ma][1], al[ma][2], al[ma][3], aA_lo + off);
            }
#pragma unroll
            for (int nb = 0; nb < 4; nb++) {
                uint32_t off = (wn + nb * 16 + lrow) * (LDK * 2) + kc * 2;
                ldsm_x4(bh[nb][0], bh[nb][1], bh[nb][2], bh[nb][3], aB_hi + off);
                ldsm_x4(bl[nb][0], bl[nb][1], bl[nb][2], bl[nb][3], aB_lo + off);
            }
#pragma unroll
            for (int ma = 0; ma < 2; ma++)
#pragma unroll
                for (int nb = 0; nb < 4; nb++) {
                    mma_bf16(acc[ma][nb * 2],     ah[ma], bh[nb][0], bh[nb][2]);
                    mma_bf16(acc[ma][nb * 2 + 1], ah[ma], bh[nb][1], bh[nb][3]);
                    mma_bf16(acc[ma][nb * 2],     ah[ma], bl[nb][0], bl[nb][2]);
                    mma_bf16(acc[ma][nb * 2 + 1], ah[ma], bl[nb][1], bl[nb][3]);
                    mma_bf16(acc[ma][nb * 2],     al[ma], bh[nb][0], bh[nb][2]);
                    mma_bf16(acc[ma][nb * 2 + 1], al[ma], bh[nb][1], bh[nb][3]);
                }
        }
        __syncthreads();
    }

    const int er = lane >> 2;
    const int ec = (lane & 3) * 2;
    if (C) {
#pragma unroll
        for (int ma = 0; ma < 2; ma++)
#pragma unroll
            for (int na = 0; na < 8; na++) {
                int row = m0 + wm + ma * 16 + er;
                int col = n0 + wn + na * 8 + ec;
                float* p0 = C + (size_t)row * N + col;
                float* p1 = C + (size_t)(row + 8) * N + col;
                p0[0] = acc[ma][na][0]; p0[1] = acc[ma][na][1];
                p1[0] = acc[ma][na][2]; p1[1] = acc[ma][na][3];
            }
    } else {
#pragma unroll
        for (int ma = 0; ma < 2; ma++)
#pragma unroll
            for (int na = 0; na < 8; na++) {
                int row = m0 + wm + ma * 16 + er;
                int col = n0 + wn + na * 8 + ec;
                size_t i0 = (size_t)row * N + col;
                size_t i1 = (size_t)(row + 8) * N + col;
                uint32_t h, l;
                split2(acc[ma][na][0], acc[ma][na][1], h, l);
                *(uint32_t*)(Chi + i0) = h; *(uint32_t*)(Clo + i0) = l;
                split2(acc[ma][na][2], acc[ma][na][3], h, l);
                *(uint32_t*)(Chi + i1) = h; *(uint32_t*)(Clo + i1) = l;
            }
    }
}

// ============================================================
// LoRA projection: bf16 hi/lo out, 16-row blocks
// ============================================================
__global__ __launch_bounds__(256) void lora_gemm(const float* __restrict__ X,
                                                 const float* __restrict__ W,
                                                 __nv_bfloat16* __restrict__ Ch,
                                                 __nv_bfloat16* __restrict__ Cl) {
    __shared__ float xs[16][33];
    __shared__ float ws[32][33];
    const int tid = threadIdx.x;
    const int lane = tid & 31, wrp = tid >> 5;  // 8 warps x 2 rows
    const int m0 = blockIdx.x * 16;
    float acc[2] = {0.f, 0.f};

    for (int k0 = 0; k0 < DIM; k0 += 32) {
        __syncthreads();
        {
            int lin = tid;                  // xs: 512 elems, 2 per thread
#pragma unroll
            for (int l = 0; l < 2; l++, lin += 256)
                xs[lin >> 5][lin & 31] = X[(size_t)(m0 + (lin >> 5)) * DIM + k0 + (lin & 31)];
            lin = tid;                      // ws: 1024 elems, 4 per thread
#pragma unroll
            for (int l = 0; l < 4; l++, lin += 256)
                ws[lin >> 5][lin & 31] = W[(size_t)(lin >> 5) * DIM + k0 + (lin & 31)];
        }
        __syncthreads();
#pragma unroll
        for (int kk = 0; kk < 32; kk++) {
            float wv = ws[lane][kk];
#pragma unroll
            for (int i = 0; i < 2; i++)
                acc[i] = fmaf(xs[wrp * 2 + i][kk], wv, acc[i]);
        }
    }
#pragma unroll
    for (int i = 0; i < 2; i++) {
        size_t idx = (size_t)(m0 + wrp * 2 + i) * RANK + lane;
        __nv_bfloat16 hv = __float2bfloat16(acc[i]);
        Ch[idx] = hv;
        Cl[idx] = __float2bfloat16(acc[i] - __bfloat162float(hv));
    }
}

// ============================================================
// RoPE in-place on bf16 hi/lo pairs of q and k
// ============================================================
__global__ __launch_bounds__(256) void rope_pair(__nv_bfloat16* __restrict__ qh,
                                                 __nv_bfloat16* __restrict__ ql,
                                                 __nv_bfloat16* __restrict__ kh,
                                                 __nv_bfloat16* __restrict__ kl,
                                                 const float* __restrict__ cs,
                                                 const float* __restrict__ sn) {
    int t = blockIdx.x * 256 + threadIdx.x;      // pair index
    int p = t & 63;
    int row = t / (DIM / 2);
    int sidx = row & (SS - 1);
    float c = cs[sidx * 64 + p];
    float si = sn[sidx * 64 + p];

    {
        __nv_bfloat162 H = ((__nv_bfloat162*)qh)[t];
        __nv_bfloat162 L = ((__nv_bfloat162*)ql)[t];
        float x = __bfloat162float(H.x) + __bfloat162float(L.x);
        float y = __bfloat162float(H.y) + __bfloat162float(L.y);
        float ox = x * c - y * si;
        float oy = x * si + y * c;
        uint32_t hv, lv;
        split2(ox, oy, hv, lv);
        ((uint32_t*)qh)[t] = hv;
        ((uint32_t*)ql)[t] = lv;
    }
    {
        __nv_bfloat162 H = ((__nv_bfloat162*)kh)[t];
        __nv_bfloat162 L = ((__nv_bfloat162*)kl)[t];
        float x = __bfloat162float(H.x) + __bfloat162float(L.x);
        float y = __bfloat162float(H.y) + __bfloat162float(L.y);
        float ox = x * c - y * si;
        float oy = x * si + y * c;
        uint32_t hv, lv;
        split2(ox, oy, hv, lv);
        ((uint32_t*)kh)[t] = hv;
        ((uint32_t*)kl)[t] = lv;
    }
}

// ============================================================
// Tensor-core flash attention, pipelined K double-buffer /
// V single-buffer prefetch. BM=128, BN=64, bf16 pair output.
// ============================================================
#define SQB 272
#define SRB 80
#define KTILE 17408            // 64 x 272
#define KSTG  (2 * KTILE)      // hi + lo per stage
#define HTILE 5120             // 64 x 80
#define HSTG  (2 * HTILE)
#define oQh 0
#define oQl 34816
#define oK  69632              // 2 stages x KSTG -> 139264
#define oV  139264             // hi + lo -> 174080
#define oqh 174080
#define oql 184320
#define okh 194560             // 2 stages x HSTG -> 215040
#define FSMEM 215040

__global__ __launch_bounds__(256) void flash_tc(
    const __nv_bfloat16* __restrict__ Qh_, const __nv_bfloat16* __restrict__ Ql_,
    const __nv_bfloat16* __restrict__ Kh_, const __nv_bfloat16* __restrict__ Kl_,
    const __nv_bfloat16* __restrict__ Vh_, const __nv_bfloat16* __restrict__ Vl_,
    const __nv_bfloat16* __restrict__ QHh_, const __nv_bfloat16* __restrict__ QHl_,
    const __nv_bfloat16* __restrict__ KHh_, const __nv_bfloat16* __restrict__ KHl_,
    __nv_bfloat16* __restrict__ Oh, __nv_bfloat16* __restrict__ Ol) {
    extern __shared__ char sm[];
    const uint32_t sb = smem_to_u32(sm);
    const int tid = threadIdx.x, lane = tid & 31, wid = tid >> 5;
    const int qt = gridDim.x - 1 - blockIdx.x;
    const int b = blockIdx.y >> 4, h = blockIdx.y & 15;
    const int q0 = qt * 128;
    const size_t rowbase = (size_t)b * SS;
    const int wm = wid * 16;
    const int lrow = lane & 15, lcol = (lane >> 4) * 8;
    const float SC = 0.08838834764831845f;

    auto issue_K = [&](int kt) {
        int nk0 = min(kt * 64, SS - 64);
        int stg = kt & 1;
        uint32_t bKh = sb + oK + stg * KSTG;
        uint32_t bKl = bKh + KTILE;
#pragma unroll
        for (int u = 0; u < 4; u++) {
            int cid = u * 256 + tid;
            int row = cid >> 4, col = cid & 15;
            size_t g = (rowbase + nk0 + row) * DIM + h * HD + col * 8;
            cp16(bKh + row * SQB + col * 16, Kh_ + g);
            cp16(bKl + row * SQB + col * 16, Kl_ + g);
        }
        uint32_t bkh = sb + okh + stg * HSTG;
        {
            int row = tid >> 2, col = tid & 3;
            size_t g = (rowbase + nk0 + row) * RANK + col * 8;
            cp16(bkh + row * SRB + col * 16, KHh_ + g);
            cp16(bkh + HTILE + row * SRB + col * 16, KHl_ + g);
        }
        CP_COMMIT();
    };
    auto issue_V = [&](int kt) {
        int nk0 = min(kt * 64, SS - 64);
#pragma unroll
        for (int u = 0; u < 4; u++) {
            int cid = u * 256 + tid;
            int row = cid >> 4, col = cid & 15;
            size_t g = (rowbase + nk0 + row) * DIM + h * HD + col * 8;
            cp16(sb + oV + row * SQB + col * 16, Vh_ + g);
            cp16(sb + oV + KTILE + row * SQB + col * 16, Vl_ + g);
        }
        CP_COMMIT();
    };

    // ---- prologue: Q + qh, then K0, then V0 ----
    {
#pragma unroll
        for (int u = 0; u < 8; u++) {
            int cid = u * 256 + tid;
            int row = cid >> 4, col = cid & 15;
            size_t g = (rowbase + q0 + row) * DIM + h * HD + col * 8;
            cp16(sb + oQh + row * SQB + col * 16, Qh_ + g);
            cp16(sb + oQl + row * SQB + col * 16, Ql_ + g);
        }
#pragma unroll
        for (int u = 0; u < 2; u++) {
            int cid = u * 256 + tid;
            int row = cid >> 2, col = cid & 3;
            size_t g = (rowbase + q0 + row) * RANK + col * 8;
            cp16(sb + oqh + row * SRB + col * 16, QHh_ + g);
            cp16(sb + oql + row * SRB + col * 16, QHl_ + g);
        }
        CP_COMMIT();
    }
    issue_K(0);
    issue_V(0);

    float o[16][4];
#pragma unroll
    for (int i = 0; i < 16; i++)
#pragma unroll
        for (int e = 0; e < 4; e++) o[i][e] = 0.f;
    float m0 = -1e30f, m1 = -1e30f, l0 = 0.f, l1 = 0.f;

    const int nkt = q0 / 64 + 2;
    for (int kt = 0; kt < nkt; kt++) {
        const int k0 = kt * 64;
        const int kb = kt & 1;
        CP_WAIT(1);          // Q (first iter) + K(kt) + kh(kt) ready
        __syncthreads();
        issue_K(kt + 1);     // prefetch next K into other stage

        const bool skip = (k0 > q0 + wm + 15);
        float s[8][4];
        if (!skip) {
            const uint32_t bKh = sb + oK + kb * KSTG, bKl = bKh + KTILE;
            const uint32_t bkh = sb + okh + kb * HSTG, bkl = bkh + HTILE;

            // gate logits
            float gg[8][4];
#pragma unroll
            for (int i = 0; i < 8; i++)
#pragma unroll
                for (int e = 0; e < 4; e++) gg[i][e] = 0.f;
#pragma unroll
            for (int ks = 0; ks < 2; ks++) {
                const int kc = ks * 16 + lcol;
                uint32_t ah[4], al[4];
                ldsm_x4(ah[0], ah[1], ah[2], ah[3], sb + oqh + (wm + lrow) * SRB + kc * 2);
                ldsm_x4(al[0], al[1], al[2], al[3], sb + oql + (wm + lrow) * SRB + kc * 2);
#pragma unroll
                for (int nb = 0; nb < 4; nb++) {
                    uint32_t bh[4], bl[4];
                    uint32_t boff = (nb * 16 + lrow) * SRB + kc * 2;
                    ldsm_x4(bh[0], bh[1], bh[2], bh[3], bkh + boff);
                    ldsm_x4(bl[0], bl[1], bl[2], bl[3], bkl + boff);
                    mma_bf16(gg[nb * 2],     ah, bh[0], bh[2]);
                    mma_bf16(gg[nb * 2],     ah, bl[0], bl[2]);
                    mma_bf16(gg[nb * 2],     al, bh[0], bh[2]);
                    mma_bf16(gg[nb * 2 + 1], ah, bh[1], bh[3]);
                    mma_bf16(gg[nb * 2 + 1], ah, bl[1], bl[3]);
                    mma_bf16(gg[nb * 2 + 1], al, bh[1], bh[3]);
                }
            }
#pragma unroll
            for (int i = 0; i < 8; i++)
#pragma unroll
                for (int e = 0; e < 4; e++)
                    gg[i][e] = 1.f / (1.f + __expf(-gg[i][e]));

            // S = Q.K^T
#pragma unroll
            for (int i = 0; i < 8; i++)
#pragma unroll
                for (int e = 0; e < 4; e++) s[i][e] = 0.f;
#pragma unroll
            for (int ks = 0; ks < 8; ks++) {
                const int kc = ks * 16 + lcol;
                uint32_t ah[4], al[4];
                ldsm_x4(ah[0], ah[1], ah[2], ah[3], sb + oQh + (wm + lrow) * SQB + kc * 2);
                ldsm_x4(al[0], al[1], al[2], al[3], sb + oQl + (wm + lrow) * SQB + kc * 2);
#pragma unroll
                for (int nb = 0; nb < 4; nb++) {
                    uint32_t bh[4], bl[4];
                    uint32_t boff = (nb * 16 + lrow) * SQB + kc * 2;
                    ldsm_x4(bh[0], bh[1], bh[2], bh[3], bKh + boff);
                    ldsm_x4(bl[0], bl[1], bl[2], bl[3], bKl + boff);
                    mma_bf16(s[nb * 2],     ah, bh[0], bh[2]);
                    mma_bf16(s[nb * 2],     ah, bl[0], bl[2]);
                    mma_bf16(s[nb * 2],     al, bh[0], bh[2]);
                    mma_bf16(s[nb * 2 + 1], ah, bh[1], bh[3]);
                    mma_bf16(s[nb * 2 + 1], ah, bl[1], bl[3]);
                    mma_bf16(s[nb * 2 + 1], al, bh[1], bh[3]);
                }
            }

            // scale + causal mask
            const int r0g = q0 + wm + (lane >> 2);
            if (k0 + 64 > q0 + wm) {
#pragma unroll
                for (int na = 0; na < 8; na++)
#pragma unroll
                    for (int e = 0; e < 4; e++) {
                        int key = k0 + na * 8 + (lane & 3) * 2 + (e & 1);
                        int row = r0g + (e >> 1) * 8;
                        s[na][e] = (key <= row) ? s[na][e] * SC : -1e30f;
                    }
            } else {
#pragma unroll
                for (int na = 0; na < 8; na++)
#pragma unroll
                    for (int e = 0; e < 4; e++) s[na][e] *= SC;
            }

            // online softmax
            float mx0 = -1e30f, mx1 = -1e30f;
#pragma unroll
            for (int na = 0; na < 8; na++) {
                mx0 = fmaxf(mx0, fmaxf(s[na][0], s[na][1]));
                mx1 = fmaxf(mx1, fmaxf(s[na][2], s[na][3]));
            }
            mx0 = fmaxf(mx0, __shfl_xor_sync(0xffffffffu, mx0, 1));
            mx0 = fmaxf(mx0, __shfl_xor_sync(0xffffffffu, mx0, 2));
            mx1 = fmaxf(mx1, __shfl_xor_sync(0xffffffffu, mx1, 1));
            mx1 = fmaxf(mx1, __shfl_xor_sync(0xffffffffu, mx1, 2));
            float mn0 = fmaxf(m0, mx0), mn1 = fmaxf(m1, mx1);
            float al0 = __expf(m0 - mn0), al1 = __expf(m1 - mn1);
            m0 = mn0; m1 = mn1;
            float rs0 = 0.f, rs1 = 0.f;
#pragma unroll
            for (int na = 0; na < 8; na++) {
                s[na][0] = __expf(s[na][0] - m0); rs0 += s[na][0];
                s[na][1] = __expf(s[na][1] - m0); rs0 += s[na][1];
                s[na][2] = __expf(s[na][2] - m1); rs1 += s[na][2];
                s[na][3] = __expf(s[na][3] - m1); rs1 += s[na][3];
            }
            rs0 += __shfl_xor_sync(0xffffffffu, rs0, 1);
            rs0 += __shfl_xor_sync(0xffffffffu, rs0, 2);
            rs1 += __shfl_xor_sync(0xffffffffu, rs1, 1);
            rs1 += __shfl_xor_sync(0xffffffffu, rs1, 2);
            l0 = l0 * al0 + rs0;
            l1 = l1 * al1 + rs1;
#pragma unroll
            for (int na = 0; na < 16; na++) {
                o[na][0] *= al0; o[na][1] *= al0;
                o[na][2] *= al1; o[na][3] *= al1;
            }
#pragma unroll
            for (int na = 0; na < 8; na++)
#pragma unroll
                for (int e = 0; e < 4; e++) s[na][e] *= gg[na][e];
        }

        CP_WAIT(1);          // V(kt) ready (K(kt+1) may pend)
        __syncthreads();

        if (!skip) {
#pragma unroll
            for (int j = 0; j < 4; j++) {
                uint32_t wa[4], wl[4];
                split2(s[2 * j][0],     s[2 * j][1],     wa[0], wl[0]);
                split2(s[2 * j][2],     s[2 * j][3],     wa[1], wl[1]);
                split2(s[2 * j + 1][0], s[2 * j + 1][1], wa[2], wl[2]);
                split2(s[2 * j + 1][2], s[2 * j + 1][3], wa[3], wl[3]);
#pragma unroll
                for (int dp = 0; dp < 8; dp++) {
                    uint32_t vh[4], vl[4];
                    uint32_t voff = (j * 16 + lrow) * SQB + (dp * 16 + lcol) * 2;
                    ldsm_x4t(vh[0], vh[1], vh[2], vh[3], sb + oV + voff);
                    ldsm_x4t(vl[0], vl[1], vl[2], vl[3], sb + oV + KTILE + voff);
                    mma_bf16(o[dp * 2],     wa, vh[0], vh[1]);
                    mma_bf16(o[dp * 2],     wa, vl[0], vl[1]);
                    mma_bf16(o[dp * 2],     wl, vh[0], vh[1]);
                    mma_bf16(o[dp * 2 + 1], wa, vh[2], vh[3]);
                    mma_bf16(o[dp * 2 + 1], wa, vl[2], vl[3]);
                    mma_bf16(o[dp * 2 + 1], wl, vh[2], vh[3]);
                }
            }
        }
        __syncthreads();     // V buffer free
        issue_V(kt + 1);
    }

    // ---- epilogue: normalized bf16 hi/lo pairs ----
    const float inv0 = 1.f / l0, inv1 = 1.f / l1;
    const int row0 = q0 + wm + (lane >> 2);
    size_t base0 = (rowbase + row0) * DIM + h * HD;
    size_t base1 = base0 + 8 * (size_t)DIM;
#pragma unroll
    for (int na = 0; na < 16; na++) {
        int d = na * 8 + (lane & 3) * 2;
        uint32_t hv, lv;
        split2(o[na][0] * inv0, o[na][1] * inv0, hv, lv);
        *(uint32_t*)(Oh + base0 + d) = hv;
        *(uint32_t*)(Ol + base0 + d) = lv;
        split2(o[na][2] * inv1, o[na][3] * inv1, hv, lv);
        *(uint32_t*)(Oh + base1 + d) = hv;
        *(uint32_t*)(Ol + base1 + d) = lv;
    }
}

// ============================================================
// launch
// ============================================================
extern "C" void kernel_launch(void* const* d_in, const int* in_sizes, int n_in,
                              void* d_out, int out_size) {
    const float* x    = (const float*)d_in[0];
    const float* fcos = (const float*)d_in[2];
    const float* fsin = (const float*)d_in[3];
    const float* wq   = (const float*)d_in[4];
    const float* wk   = (const float*)d_in[5];
    const float* wv   = (const float*)d_in[6];
    const float* wo   = (const float*)d_in[7];
    const float* waq  = (const float*)d_in[8];
    const float* wak  = (const float*)d_in[9];
    float* out = (float*)d_out;

    __nv_bfloat16 *gxh, *gxl, *gaoh, *gaol, *gwh, *gwl;
    __nv_bfloat16 *qbh, *qbl, *kbh, *kbl, *vbh, *vbl, *qhh, *qhl, *khh, *khl;
    cudaGetSymbolAddress((void**)&gxh, g_xh);
    cudaGetSymbolAddress((void**)&gxl, g_xl);
    cudaGetSymbolAddress((void**)&gaoh, g_aoh);
    cudaGetSymbolAddress((void**)&gaol, g_aol);
    cudaGetSymbolAddress((void**)&gwh, g_wh);
    cudaGetSymbolAddress((void**)&gwl, g_wl);
    cudaGetSymbolAddress((void**)&qbh, g_qbh);
    cudaGetSymbolAddress((void**)&qbl, g_qbl);
    cudaGetSymbolAddress((void**)&kbh, g_kbh);
    cudaGetSymbolAddress((void**)&kbl, g_kbl);
    cudaGetSymbolAddress((void**)&vbh, g_vbh);
    cudaGetSymbolAddress((void**)&vbl, g_vbl);
    cudaGetSymbolAddress((void**)&qhh, g_qhh);
    cudaGetSymbolAddress((void**)&qhl, g_qhl);
    cudaGetSymbolAddress((void**)&khh, g_khh);
    cudaGetSymbolAddress((void**)&khl, g_khl);

    cudaFuncSetAttribute(tc_gemm, cudaFuncAttributeMaxDynamicSharedMemorySize, TC_SMEM);
    cudaFuncSetAttribute(flash_tc, cudaFuncAttributeMaxDynamicSharedMemorySize, FSMEM);

    const int XB = MROWS * DIM / 4 / 256;
    const int WB = DIM * DIM / 4 / 256;

    f32_to_bf16pair<<<XB, 256>>>(x,  gxh, gxl);
    f32_to_bf16pair<<<WB, 256>>>(wq, gwh + 0 * (size_t)DIM * DIM, gwl + 0 * (size_t)DIM * DIM);
    f32_to_bf16pair<<<WB, 256>>>(wk, gwh + 1 * (size_t)DIM * DIM, gwl + 1 * (size_t)DIM * DIM);
    f32_to_bf16pair<<<WB, 256>>>(wv, gwh + 2 * (size_t)DIM * DIM, gwl + 2 * (size_t)DIM * DIM);
    f32_to_bf16pair<<<WB, 256>>>(wo, gwh + 3 * (size_t)DIM * DIM, gwl + 3 * (size_t)DIM * DIM);

    dim3 gg(DIM / 128, MROWS / 128);
    tc_gemm<<<gg, 256, TC_SMEM>>>(gxh, gxl, gwh + 0 * (size_t)DIM * DIM, gwl + 0 * (size_t)DIM * DIM, nullptr, qbh, qbl, DIM);
    tc_gemm<<<gg, 256, TC_SMEM>>>(gxh, gxl, gwh + 1 * (size_t)DIM * DIM, gwl + 1 * (size_t)DIM * DIM, nullptr, kbh, kbl, DIM);
    tc_gemm<<<gg, 256, TC_SMEM>>>(gxh, gxl, gwh + 2 * (size_t)DIM * DIM, gwl + 2 * (size_t)DIM * DIM, nullptr, vbh, vbl, DIM);
    lora_gemm<<<MROWS / 16, 256>>>(x, waq, qhh, qhl);
    lora_gemm<<<MROWS / 16, 256>>>(x, wak, khh, khl);

    rope_pair<<<MROWS * (DIM / 2) / 256, 256>>>(qbh, qbl, kbh, kbl, fcos, fsin);

    flash_tc<<<dim3(SS / 128, BB * NH), 256, FSMEM>>>(qbh, qbl, kbh, kbl, vbh, vbl,
                                                      qhh, qhl, khh, khl, gaoh, gaol);

    tc_gemm<<<gg, 256, TC_SMEM>>>(gaoh, gaol, gwh + 3 * (size_t)DIM * DIM, gwl + 3 * (size_t)DIM * DIM, out, nullptr, nullptr, DIM);
}